// round 3
// baseline (speedup 1.0000x reference)
#include <cuda_runtime.h>
#include <cuda_bf16.h>
#include <math.h>

#define NEP 256
#define NS  32
#define DIN 512
#define DF  512
#define T   1026
#define TT  513
#define R2  8      // z-rows per block in logvar kernel
#define CH  64     // t-chunk in pairwise kernel

#define LOG_2PIE 2.8378770664093453f

// -------- device scratch (no allocations allowed) --------
__device__ float g_mu [2][NEP][T];   // z (mu)
__device__ float g_elv[2][NEP][T];   // exp(lv)
__device__ float g_eml[2][NEP][T];   // exp(-lv)
__device__ float g_H  [2][NEP];
__device__ float g_score[NEP][NEP];

// bf16 split operands. Inputs: [set][8192 rows][512 k] as packed half-pairs
__device__ unsigned g_ihi[2][8192 * 256];
__device__ unsigned g_ilo[2][8192 * 256];
// W split, k-pair interleaved: word (k2, n) holds halves (k=2*k2, 2*k2+1) of column n
__device__ unsigned g_wphi[256 * 512];
__device__ unsigned g_wplo[256 * 512];

// ============================================================
__device__ __forceinline__ void split1(float x, unsigned short& h, unsigned short& l)
{
    __nv_bfloat16 bh = __float2bfloat16(x);
    float r = x - __bfloat162float(bh);
    __nv_bfloat16 bl = __float2bfloat16(r);
    h = __bfloat16_as_ushort(bh);
    l = __bfloat16_as_ushort(bl);
}

__global__ void k_split_in(const float* __restrict__ trin, const float* __restrict__ tein)
{
    const int set = blockIdx.z;
    const unsigned w = blockIdx.x * 256 + threadIdx.x;   // 2,097,152 words per set
    const float2* src = (const float2*)(set ? tein : trin);
    float2 v = src[w];
    unsigned short h0, l0, h1, l1;
    split1(v.x, h0, l0);
    split1(v.y, h1, l1);
    g_ihi[set][w] = (unsigned)h0 | ((unsigned)h1 << 16);
    g_ilo[set][w] = (unsigned)l0 | ((unsigned)l1 << 16);
}

__global__ void k_split_w(const float* __restrict__ Wfe)
{
    const unsigned w = blockIdx.x * 256 + threadIdx.x;   // 131072 words
    const int k2 = w >> 9;
    const int n  = w & 511;
    float x0 = Wfe[(size_t)(2 * k2) * DF + n];
    float x1 = Wfe[(size_t)(2 * k2 + 1) * DF + n];
    unsigned short h0, l0, h1, l1;
    split1(x0, h0, l0);
    split1(x1, h1, l1);
    g_wphi[w] = (unsigned)h0 | ((unsigned)h1 << 16);
    g_wplo[w] = (unsigned)l0 | ((unsigned)l1 << 16);
}

__global__ void k_targets(const float* __restrict__ trtg, const float* __restrict__ tetg)
{
    const int t = blockIdx.x * blockDim.x + threadIdx.x;
    if (t >= 512) return;
    const int set = t >> 8;
    const int e   = t & 255;
    const float* tg = (set ? tetg : trtg) + (size_t)e * NS;
    float s = 0.f;
    #pragma unroll
    for (int n = 0; n < NS; n++) s += tg[n];
    float m = s * (1.f / NS);
    float q = 0.f;
    #pragma unroll
    for (int n = 0; n < NS; n++) { float d = tg[n] - m; q = fmaf(d, d, q); }
    g_mu[set][e][0]  = m;
    g_mu[set][e][TT] = sqrtf(q * (1.f / (NS - 1)));
}

// ============================================================
// K1: tensor-core feature GEMM + fused bias/relu/mean/std epilogue.
// Block: 4 episodes (M=128) x 128 features, K=512, 2-term bf16 split (3 HMMA terms).
// grid (4 coltiles, 64 epgroups, 2 sets), 512 threads (16 warps, 4x4 warp grid).
// ============================================================
__device__ __forceinline__ void mma16816(float* d, const unsigned* a, const unsigned* b)
{
    asm volatile(
        "mma.sync.aligned.m16n8k16.row.col.f32.bf16.bf16.f32 "
        "{%0,%1,%2,%3}, {%4,%5,%6,%7}, {%8,%9}, {%0,%1,%2,%3};\n"
        : "+f"(d[0]), "+f"(d[1]), "+f"(d[2]), "+f"(d[3])
        : "r"(a[0]), "r"(a[1]), "r"(a[2]), "r"(a[3]), "r"(b[0]), "r"(b[1]));
}

#define AS_STRIDE 36   // uint32 words per A row (72 halves)
#define BS_STRIDE 132  // uint32 words per B k2-row / floats per C row

__global__ __launch_bounds__(512, 1)
void k_fgemm(const float* __restrict__ bfe)
{
    extern __shared__ unsigned char smem[];
    unsigned* Aw0 = (unsigned*)(smem);
    unsigned* Aw1 = (unsigned*)(smem + 18432);
    unsigned* Bw0 = (unsigned*)(smem + 36864);
    unsigned* Bw1 = (unsigned*)(smem + 36864 + 16896);
    float*    Cs  = (float*)(smem);          // aliased after mainloop

    const int ct  = blockIdx.x;
    const int eg  = blockIdx.y;
    const int set = blockIdx.z;
    const int tid = threadIdx.x;
    const int wid = tid >> 5;
    const int lid = tid & 31;
    const int wm  = wid >> 2;
    const int wn  = wid & 3;
    const int gid = lid >> 2;
    const int tig = lid & 3;

    const unsigned* gih = g_ihi[set];
    const unsigned* gil = g_ilo[set];

    float acc[2][4][4];
    #pragma unroll
    for (int mt = 0; mt < 2; mt++)
        #pragma unroll
        for (int nt = 0; nt < 4; nt++)
            #pragma unroll
            for (int r = 0; r < 4; r++) acc[mt][nt][r] = 0.f;

    for (int chunk = 0; chunk < 8; chunk++) {
        __syncthreads();
        #pragma unroll
        for (int i = 0; i < 8; i++) {
            int idx = tid + i * 512;
            int row = idx >> 5, kp = idx & 31;
            unsigned srci = (unsigned)(eg * 128 + row) * 256 + chunk * 32 + kp;
            Aw0[row * AS_STRIDE + kp] = gih[srci];
            Aw1[row * AS_STRIDE + kp] = gil[srci];
        }
        #pragma unroll
        for (int i = 0; i < 8; i++) {
            int idx = tid + i * 512;
            int k2 = idx >> 7, nl = idx & 127;
            unsigned srci = (unsigned)(chunk * 32 + k2) * 512 + ct * 128 + nl;
            Bw0[k2 * BS_STRIDE + nl] = g_wphi[srci];
            Bw1[k2 * BS_STRIDE + nl] = g_wplo[srci];
        }
        __syncthreads();

        #pragma unroll
        for (int ks = 0; ks < 4; ks++) {
            unsigned a[2][2][4];
            unsigned b[4][2][2];
            const int cw = ks * 8 + tig;
            #pragma unroll
            for (int mt = 0; mt < 2; mt++) {
                int r0 = wm * 32 + mt * 16 + gid;
                a[mt][0][0] = Aw0[r0 * AS_STRIDE + cw];
                a[mt][0][1] = Aw0[(r0 + 8) * AS_STRIDE + cw];
                a[mt][0][2] = Aw0[r0 * AS_STRIDE + cw + 4];
                a[mt][0][3] = Aw0[(r0 + 8) * AS_STRIDE + cw + 4];
                a[mt][1][0] = Aw1[r0 * AS_STRIDE + cw];
                a[mt][1][1] = Aw1[(r0 + 8) * AS_STRIDE + cw];
                a[mt][1][2] = Aw1[r0 * AS_STRIDE + cw + 4];
                a[mt][1][3] = Aw1[(r0 + 8) * AS_STRIDE + cw + 4];
            }
            #pragma unroll
            for (int nt = 0; nt < 4; nt++) {
                int n = wn * 32 + nt * 8 + gid;
                b[nt][0][0] = Bw0[(ks * 8 + tig) * BS_STRIDE + n];
                b[nt][0][1] = Bw0[(ks * 8 + tig + 4) * BS_STRIDE + n];
                b[nt][1][0] = Bw1[(ks * 8 + tig) * BS_STRIDE + n];
                b[nt][1][1] = Bw1[(ks * 8 + tig + 4) * BS_STRIDE + n];
            }
            #pragma unroll
            for (int mt = 0; mt < 2; mt++)
                #pragma unroll
                for (int nt = 0; nt < 4; nt++) {
                    mma16816(acc[mt][nt], a[mt][0], b[nt][0]);
                    mma16816(acc[mt][nt], a[mt][0], b[nt][1]);
                    mma16816(acc[mt][nt], a[mt][1], b[nt][0]);
                }
        }
    }

    __syncthreads();
    #pragma unroll
    for (int mt = 0; mt < 2; mt++) {
        int r0 = wm * 32 + mt * 16 + gid;
        #pragma unroll
        for (int nt = 0; nt < 4; nt++) {
            int c = wn * 32 + nt * 8 + tig * 2;
            *(float2*)&Cs[r0 * BS_STRIDE + c]       = make_float2(acc[mt][nt][0], acc[mt][nt][1]);
            *(float2*)&Cs[(r0 + 8) * BS_STRIDE + c] = make_float2(acc[mt][nt][2], acc[mt][nt][3]);
        }
    }
    __syncthreads();

    {
        const int ep = tid >> 7;
        const int j  = tid & 127;
        const int f  = ct * 128 + j;
        const float bias = bfe[f];
        float s = 0.f, ss = 0.f;
        #pragma unroll
        for (int m = 0; m < NS; m++) {
            float v = Cs[(ep * 32 + m) * BS_STRIDE + j] + bias;
            v = fmaxf(v, 0.f);
            s += v;
            ss = fmaf(v, v, ss);
        }
        float mean = s * (1.f / NS);
        float var  = (ss - s * mean) * (1.f / (NS - 1));
        float stdv = sqrtf(fmaxf(var, 0.f));
        int e = eg * 4 + ep;
        g_mu[set][e][1 + f]      = mean;
        g_mu[set][e][TT + 1 + f] = stdv;
    }
}

// ============================================================
// K2: logvar GEMM + clip/exp/H (unchanged)
// ============================================================
__global__ void k_logvar(const float* __restrict__ Wlv, const float* __restrict__ blv)
{
    const int set = blockIdx.y;
    const int r0  = blockIdx.x * R2;
    __shared__ float sz[R2][1028];
    __shared__ float sH[R2];
    const int tid = threadIdx.x;

    for (int idx = tid; idx < R2 * 1028; idx += 256) {
        int r = idx / 1028, k = idx % 1028;
        sz[r][k] = (k < T) ? g_mu[set][r0 + r][k] : 0.f;
    }
    if (tid < R2) sH[tid] = 0.f;
    __syncthreads();

    float hpart[R2];
    #pragma unroll
    for (int r = 0; r < R2; r++) hpart[r] = 0.f;

    for (int t = tid; t < T; t += 256) {
        float acc[R2];
        {
            float b = blv[t];
            #pragma unroll
            for (int r = 0; r < R2; r++) acc[r] = b;
        }
        for (int k4 = 0; k4 < 256; k4++) {
            const int k = k4 * 4;
            float w0 = Wlv[(size_t)(k + 0) * T + t];
            float w1 = Wlv[(size_t)(k + 1) * T + t];
            float w2 = Wlv[(size_t)(k + 2) * T + t];
            float w3 = Wlv[(size_t)(k + 3) * T + t];
            #pragma unroll
            for (int r = 0; r < R2; r++) {
                float4 v = ((const float4*)&sz[r][0])[k4];
                acc[r] = fmaf(v.x, w0, acc[r]);
                acc[r] = fmaf(v.y, w1, acc[r]);
                acc[r] = fmaf(v.z, w2, acc[r]);
                acc[r] = fmaf(v.w, w3, acc[r]);
            }
        }
        #pragma unroll
        for (int k = 1024; k < T; k++) {
            float w = Wlv[(size_t)k * T + t];
            #pragma unroll
            for (int r = 0; r < R2; r++) acc[r] = fmaf(sz[r][k], w, acc[r]);
        }
        #pragma unroll
        for (int r = 0; r < R2; r++) {
            float lv = fminf(fmaxf(acc[r], -9.f), -2.f);
            hpart[r] += lv;
            g_elv[set][r0 + r][t] = expf(lv);
            g_eml[set][r0 + r][t] = expf(-lv);
        }
    }
    #pragma unroll
    for (int r = 0; r < R2; r++) atomicAdd(&sH[r], hpart[r]);
    __syncthreads();
    if (tid < R2) g_H[set][r0 + tid] = sH[tid] + 0.5f * (float)T * LOG_2PIE;
}

// ============================================================
// K3: pairwise score (unchanged)
// ============================================================
__global__ void k_pair()
{
    __shared__ float sm1[16][CH + 1], se1[16][CH + 1], sq1[16][CH + 1];
    __shared__ float sm2[16][CH + 1], se2[16][CH + 1], sq2[16][CH + 1];
    const int tid = threadIdx.x;
    const int ty = tid >> 4, tx = tid & 15;
    const int i = blockIdx.y * 16 + ty;
    const int j = blockIdx.x * 16 + tx;

    float acc = 0.f;
    for (int c0 = 0; c0 < T; c0 += CH) {
        __syncthreads();
        for (int u = tid; u < 16 * CH; u += 256) {
            int rr = u / CH, t = u % CH;
            int tg = c0 + t;
            bool ok = tg < T;
            int ii = blockIdx.y * 16 + rr;
            int jj = blockIdx.x * 16 + rr;
            sm1[rr][t] = ok ? g_mu [0][ii][tg] : 0.f;
            se1[rr][t] = ok ? g_elv[0][ii][tg] : 0.f;
            sq1[rr][t] = ok ? g_eml[0][ii][tg] : 0.f;
            sm2[rr][t] = ok ? g_mu [1][jj][tg] : 0.f;
            se2[rr][t] = ok ? g_elv[1][jj][tg] : 0.f;
            sq2[rr][t] = ok ? g_eml[1][jj][tg] : 0.f;
        }
        __syncthreads();
        #pragma unroll 8
        for (int t = 0; t < CH; t++) {
            float m1 = sm1[ty][t], e1 = se1[ty][t], q1 = sq1[ty][t];
            float m2 = sm2[tx][t], e2 = se2[tx][t], q2 = sq2[tx][t];
            float d = m1 - m2;
            float dd = d * d;
            acc = fmaf(e1 + dd, q2, acc);
            acc = fmaf(e2 + dd, q1, acc);
        }
    }
    g_score[i][j] = 0.5f * acc - (float)T + g_H[0][i] + g_H[1][j];
}

// ============================================================
__global__ void k_softmax(float* __restrict__ out)
{
    const int i = blockIdx.x;
    const int j = threadIdx.x;
    __shared__ float red[256];
    float v = -g_score[i][j];
    red[j] = v;
    __syncthreads();
    for (int s = 128; s > 0; s >>= 1) {
        if (j < s) red[j] = fmaxf(red[j], red[j + s]);
        __syncthreads();
    }
    float mx = red[0];
    __syncthreads();
    float ex = expf(v - mx);
    red[j] = ex;
    __syncthreads();
    for (int s = 128; s > 0; s >>= 1) {
        if (j < s) red[j] += red[j + s];
        __syncthreads();
    }
    float lse = mx + logf(red[0]);
    out[(size_t)i * NEP + j] = v - lse;
}

__global__ void k_classes(float* __restrict__ out, int n)
{
    int k = blockIdx.x * blockDim.x + threadIdx.x;
    if (k < n) out[NEP * NEP + k] = (float)k;
}

// ============================================================
extern "C" void kernel_launch(void* const* d_in, const int* in_sizes, int n_in,
                              void* d_out, int out_size)
{
    const float* train_inputs  = (const float*)d_in[0];
    const float* train_targets = (const float*)d_in[1];
    const float* test_inputs   = (const float*)d_in[2];
    const float* test_targets  = (const float*)d_in[3];
    const float* W_fe          = (const float*)d_in[4];
    const float* b_fe          = (const float*)d_in[5];
    const float* W_lv          = (const float*)d_in[6];
    const float* b_lv          = (const float*)d_in[7];
    float* out = (float*)d_out;

    const int smem_fgemm = 70656;
    cudaFuncSetAttribute(k_fgemm, cudaFuncAttributeMaxDynamicSharedMemorySize, smem_fgemm);

    k_split_in<<<dim3(8192, 1, 2), 256>>>(train_inputs, test_inputs);
    k_split_w<<<512, 256>>>(W_fe);
    k_targets<<<2, 256>>>(train_targets, test_targets);
    k_fgemm<<<dim3(4, 64, 2), 512, smem_fgemm>>>(b_fe);
    k_logvar<<<dim3(NEP / R2, 2), 256>>>(W_lv, b_lv);
    k_pair<<<dim3(16, 16), 256>>>();
    k_softmax<<<NEP, 256>>>(out);

    int rem = out_size - NEP * NEP;
    if (rem > 0) {
        k_classes<<<(rem + 255) / 256, 256>>>(out, rem);
    }
}

// round 4
// speedup vs baseline: 2.7945x; 2.7945x over previous
#include <cuda_runtime.h>
#include <cuda_bf16.h>
#include <math.h>

#define NEP 256
#define NS  32
#define DIN 512
#define DF  512
#define T   1026
#define TT  513
#define CH  64     // t-chunk in pairwise kernel

#define LOG_2PIE 2.8378770664093453f

// K geometry for the logvar GEMM: K=1026 -> 513 k-pairs -> pad to 544 (17 chunks of 32)
#define LV_KP   544
#define LV_NPAD 1152   // 9 tiles of 128

// -------- device scratch (no allocations allowed) --------
__device__ float g_mu [2][NEP][T];   // z (mu)
__device__ float g_elv[2][NEP][T];   // exp(lv)
__device__ float g_eml[2][NEP][T];   // exp(-lv)
__device__ float g_H  [2][NEP];
__device__ float g_Hpart[9][512];    // per-Ntile partial sums of lv per row
__device__ float g_score[NEP][NEP];

// bf16 split operands. Inputs: [set][8192 rows][256 k-pair words]
__device__ __align__(16) unsigned g_ihi[2][8192 * 256];
__device__ __align__(16) unsigned g_ilo[2][8192 * 256];
// W_fe split, k-pair interleaved: word (k2, n) holds halves (k=2*k2, 2*k2+1) of column n
__device__ __align__(16) unsigned g_wphi[256 * 512];
__device__ __align__(16) unsigned g_wplo[256 * 512];
// z split: [512 rows (set*256+e)][544 k-pair words]
__device__ __align__(16) unsigned g_zhi[512 * LV_KP];
__device__ __align__(16) unsigned g_zlo[512 * LV_KP];
// W_lv split: word (k2, n): halves of rows 2k2, 2k2+1 of column n; padded
__device__ __align__(16) unsigned g_wlvh[LV_KP * LV_NPAD];
__device__ __align__(16) unsigned g_wlvl[LV_KP * LV_NPAD];

// ============================================================
__device__ __forceinline__ void split1(float x, unsigned short& h, unsigned short& l)
{
    __nv_bfloat16 bh = __float2bfloat16(x);
    float r = x - __bfloat162float(bh);
    __nv_bfloat16 bl = __float2bfloat16(r);
    h = __bfloat16_as_ushort(bh);
    l = __bfloat16_as_ushort(bl);
}

__device__ __forceinline__ void cp16(unsigned saddr, const void* g)
{
    asm volatile("cp.async.cg.shared.global [%0], [%1], 16;\n" :: "r"(saddr), "l"(g));
}
__device__ __forceinline__ unsigned s2u(const void* p)
{
    return (unsigned)__cvta_generic_to_shared(p);
}

__global__ void k_split_in(const float* __restrict__ trin, const float* __restrict__ tein)
{
    const int set = blockIdx.z;
    const unsigned w = blockIdx.x * 256 + threadIdx.x;   // 2,097,152 words per set
    const float2* src = (const float2*)(set ? tein : trin);
    float2 v = src[w];
    unsigned short h0, l0, h1, l1;
    split1(v.x, h0, l0);
    split1(v.y, h1, l1);
    g_ihi[set][w] = (unsigned)h0 | ((unsigned)h1 << 16);
    g_ilo[set][w] = (unsigned)l0 | ((unsigned)l1 << 16);
}

__global__ void k_split_w(const float* __restrict__ Wfe)
{
    const unsigned w = blockIdx.x * 256 + threadIdx.x;   // 131072 words
    const int k2 = w >> 9;
    const int n  = w & 511;
    float x0 = Wfe[(size_t)(2 * k2) * DF + n];
    float x1 = Wfe[(size_t)(2 * k2 + 1) * DF + n];
    unsigned short h0, l0, h1, l1;
    split1(x0, h0, l0);
    split1(x1, h1, l1);
    g_wphi[w] = (unsigned)h0 | ((unsigned)h1 << 16);
    g_wplo[w] = (unsigned)l0 | ((unsigned)l1 << 16);
}

__global__ void k_split_z()
{
    const unsigned idx = blockIdx.x * 256 + threadIdx.x;   // 512*544 = 278528
    if (idx >= 512u * LV_KP) return;
    const int row = idx / LV_KP;
    const int k2  = idx % LV_KP;
    const int set = row >> 8, e = row & 255;
    const int k = 2 * k2;
    float x0 = (k     < T) ? g_mu[set][e][k]     : 0.f;
    float x1 = (k + 1 < T) ? g_mu[set][e][k + 1] : 0.f;
    unsigned short h0, l0, h1, l1;
    split1(x0, h0, l0);
    split1(x1, h1, l1);
    g_zhi[idx] = (unsigned)h0 | ((unsigned)h1 << 16);
    g_zlo[idx] = (unsigned)l0 | ((unsigned)l1 << 16);
}

__global__ void k_split_wlv(const float* __restrict__ Wlv)
{
    const unsigned idx = blockIdx.x * 256 + threadIdx.x;   // 544*1152 = 626688
    if (idx >= (unsigned)LV_KP * LV_NPAD) return;
    const int k2 = idx / LV_NPAD;
    const int n  = idx % LV_NPAD;
    const int k = 2 * k2;
    float x0 = (k     < T && n < T) ? Wlv[(size_t)k * T + n]       : 0.f;
    float x1 = (k + 1 < T && n < T) ? Wlv[(size_t)(k + 1) * T + n] : 0.f;
    unsigned short h0, l0, h1, l1;
    split1(x0, h0, l0);
    split1(x1, h1, l1);
    g_wlvh[idx] = (unsigned)h0 | ((unsigned)h1 << 16);
    g_wlvl[idx] = (unsigned)l0 | ((unsigned)l1 << 16);
}

__global__ void k_targets(const float* __restrict__ trtg, const float* __restrict__ tetg)
{
    const int t = blockIdx.x * blockDim.x + threadIdx.x;
    if (t >= 512) return;
    const int set = t >> 8;
    const int e   = t & 255;
    const float* tg = (set ? tetg : trtg) + (size_t)e * NS;
    float s = 0.f;
    #pragma unroll
    for (int n = 0; n < NS; n++) s += tg[n];
    float m = s * (1.f / NS);
    float q = 0.f;
    #pragma unroll
    for (int n = 0; n < NS; n++) { float d = tg[n] - m; q = fmaf(d, d, q); }
    g_mu[set][e][0]  = m;
    g_mu[set][e][TT] = sqrtf(q * (1.f / (NS - 1)));
}

// ============================================================
// mma helper
// ============================================================
__device__ __forceinline__ void mma16816(float* d, const unsigned* a, const unsigned* b)
{
    asm volatile(
        "mma.sync.aligned.m16n8k16.row.col.f32.bf16.bf16.f32 "
        "{%0,%1,%2,%3}, {%4,%5,%6,%7}, {%8,%9}, {%0,%1,%2,%3};\n"
        : "+f"(d[0]), "+f"(d[1]), "+f"(d[2]), "+f"(d[3])
        : "r"(a[0]), "r"(a[1]), "r"(a[2]), "r"(a[3]), "r"(b[0]), "r"(b[1]));
}

#define AS_STRIDE 36   // uint32 words per A row (72 halves)
#define BS_STRIDE 132  // uint32 words per B k2-row / floats per C row

// ============================================================
// K1: tensor-core feature GEMM, cp.async double-buffered,
// fused bias/relu/mean/std epilogue.
// grid (4 coltiles, 64 epgroups, 2 sets), 512 threads.
// dyn smem = 2 * 70656 = 141312
// ============================================================
#define FG_BUF 70656

__global__ __launch_bounds__(512, 1)
void k_fgemm(const float* __restrict__ bfe)
{
    extern __shared__ unsigned char smem[];
    const int ct  = blockIdx.x;
    const int eg  = blockIdx.y;
    const int set = blockIdx.z;
    const int tid = threadIdx.x;
    const int wid = tid >> 5;
    const int lid = tid & 31;
    const int wm  = wid >> 2;
    const int wn  = wid & 3;
    const int gid = lid >> 2;
    const int tig = lid & 3;

    const unsigned* gih = g_ihi[set];
    const unsigned* gil = g_ilo[set];

    float acc[2][4][4];
    #pragma unroll
    for (int mt = 0; mt < 2; mt++)
        #pragma unroll
        for (int nt = 0; nt < 4; nt++)
            #pragma unroll
            for (int r = 0; r < 4; r++) acc[mt][nt][r] = 0.f;

    // ---- stage chunk `c` into buffer `buf` via cp.async ----
    auto stage = [&](int c, int buf) {
        unsigned* Aw0 = (unsigned*)(smem + buf * FG_BUF);
        unsigned* Aw1 = (unsigned*)(smem + buf * FG_BUF + 18432);
        unsigned* Bw0 = (unsigned*)(smem + buf * FG_BUF + 36864);
        unsigned* Bw1 = (unsigned*)(smem + buf * FG_BUF + 53760);
        #pragma unroll
        for (int i = 0; i < 2; i++) {
            int u = tid + i * 512;                 // 1024 16B units per term
            int row = u >> 3, kp = (u & 7) * 4;
            unsigned srci = (unsigned)(eg * 128 + row) * 256 + c * 32 + kp;
            cp16(s2u(&Aw0[row * AS_STRIDE + kp]), &gih[srci]);
            cp16(s2u(&Aw1[row * AS_STRIDE + kp]), &gil[srci]);
        }
        #pragma unroll
        for (int i = 0; i < 2; i++) {
            int u = tid + i * 512;
            int k2 = u >> 5, nl = (u & 31) * 4;
            unsigned srci = (unsigned)(c * 32 + k2) * 512 + ct * 128 + nl;
            cp16(s2u(&Bw0[k2 * BS_STRIDE + nl]), &g_wphi[srci]);
            cp16(s2u(&Bw1[k2 * BS_STRIDE + nl]), &g_wplo[srci]);
        }
        asm volatile("cp.async.commit_group;\n" ::: "memory");
    };

    stage(0, 0);

    for (int chunk = 0; chunk < 8; chunk++) {
        if (chunk < 7) {
            stage(chunk + 1, (chunk + 1) & 1);
            asm volatile("cp.async.wait_group 1;\n" ::: "memory");
        } else {
            asm volatile("cp.async.wait_group 0;\n" ::: "memory");
        }
        __syncthreads();

        const int buf = chunk & 1;
        unsigned* Aw0 = (unsigned*)(smem + buf * FG_BUF);
        unsigned* Aw1 = (unsigned*)(smem + buf * FG_BUF + 18432);
        unsigned* Bw0 = (unsigned*)(smem + buf * FG_BUF + 36864);
        unsigned* Bw1 = (unsigned*)(smem + buf * FG_BUF + 53760);

        #pragma unroll
        for (int ks = 0; ks < 4; ks++) {
            unsigned a[2][2][4];
            unsigned b[4][2][2];
            const int cw = ks * 8 + tig;
            #pragma unroll
            for (int mt = 0; mt < 2; mt++) {
                int r0 = wm * 32 + mt * 16 + gid;
                a[mt][0][0] = Aw0[r0 * AS_STRIDE + cw];
                a[mt][0][1] = Aw0[(r0 + 8) * AS_STRIDE + cw];
                a[mt][0][2] = Aw0[r0 * AS_STRIDE + cw + 4];
                a[mt][0][3] = Aw0[(r0 + 8) * AS_STRIDE + cw + 4];
                a[mt][1][0] = Aw1[r0 * AS_STRIDE + cw];
                a[mt][1][1] = Aw1[(r0 + 8) * AS_STRIDE + cw];
                a[mt][1][2] = Aw1[r0 * AS_STRIDE + cw + 4];
                a[mt][1][3] = Aw1[(r0 + 8) * AS_STRIDE + cw + 4];
            }
            #pragma unroll
            for (int nt = 0; nt < 4; nt++) {
                int n = wn * 32 + nt * 8 + gid;
                b[nt][0][0] = Bw0[cw * BS_STRIDE + n];
                b[nt][0][1] = Bw0[(cw + 4) * BS_STRIDE + n];
                b[nt][1][0] = Bw1[cw * BS_STRIDE + n];
                b[nt][1][1] = Bw1[(cw + 4) * BS_STRIDE + n];
            }
            #pragma unroll
            for (int mt = 0; mt < 2; mt++)
                #pragma unroll
                for (int nt = 0; nt < 4; nt++) {
                    mma16816(acc[mt][nt], a[mt][0], b[nt][0]);
                    mma16816(acc[mt][nt], a[mt][0], b[nt][1]);
                    mma16816(acc[mt][nt], a[mt][1], b[nt][0]);
                }
        }
        __syncthreads();
    }

    // epilogue: C in smem (alias buffer 0), fused stats
    float* Cs = (float*)smem;
    #pragma unroll
    for (int mt = 0; mt < 2; mt++) {
        int r0 = wm * 32 + mt * 16 + gid;
        #pragma unroll
        for (int nt = 0; nt < 4; nt++) {
            int c = wn * 32 + nt * 8 + tig * 2;
            *(float2*)&Cs[r0 * BS_STRIDE + c]       = make_float2(acc[mt][nt][0], acc[mt][nt][1]);
            *(float2*)&Cs[(r0 + 8) * BS_STRIDE + c] = make_float2(acc[mt][nt][2], acc[mt][nt][3]);
        }
    }
    __syncthreads();

    {
        const int ep = tid >> 7;
        const int j  = tid & 127;
        const int f  = ct * 128 + j;
        const float bias = bfe[f];
        float s = 0.f, ss = 0.f;
        #pragma unroll
        for (int m = 0; m < NS; m++) {
            float v = Cs[(ep * 32 + m) * BS_STRIDE + j] + bias;
            v = fmaxf(v, 0.f);
            s += v;
            ss = fmaf(v, v, ss);
        }
        float mean = s * (1.f / NS);
        float var  = (ss - s * mean) * (1.f / (NS - 1));
        float stdv = sqrtf(fmaxf(var, 0.f));
        int e = eg * 4 + ep;
        g_mu[set][e][1 + f]      = mean;
        g_mu[set][e][TT + 1 + f] = stdv;
    }
}

// ============================================================
// K2: logvar GEMM on tensor cores.
// M=512 (set*256+e), N padded 1152, K padded 544 pairs (17 chunks of 32).
// Block: M-tile 64 x N-tile 128, 512 threads (16 warps, 4x4).
// grid (9 ntiles, 8 mtiles). Epilogue: +b_lv, clip, exp(+-lv), partial H.
// dyn smem = 52224
// ============================================================
__global__ __launch_bounds__(512, 1)
void k_lvgemm(const float* __restrict__ blv)
{
    extern __shared__ unsigned char smem[];
    unsigned* Aw0 = (unsigned*)(smem);
    unsigned* Aw1 = (unsigned*)(smem + 9216);
    unsigned* Bw0 = (unsigned*)(smem + 18432);
    unsigned* Bw1 = (unsigned*)(smem + 18432 + 16896);

    const int bn  = blockIdx.x;     // N tile (128 cols)
    const int bm  = blockIdx.y;     // M tile (64 rows)
    const int tid = threadIdx.x;
    const int wid = tid >> 5;
    const int lid = tid & 31;
    const int wm  = wid >> 2;       // 0..3, 16 rows each
    const int wn  = wid & 3;        // 0..3, 32 cols each
    const int gid = lid >> 2;
    const int tig = lid & 3;

    float acc[4][4];
    #pragma unroll
    for (int nt = 0; nt < 4; nt++)
        #pragma unroll
        for (int r = 0; r < 4; r++) acc[nt][r] = 0.f;

    for (int chunk = 0; chunk < 17; chunk++) {
        __syncthreads();
        // A: 64 rows x 32 words (per term) = 2048 words
        #pragma unroll
        for (int i = 0; i < 4; i++) {
            int idx = tid + i * 512;
            int row = idx >> 5, kp = idx & 31;
            unsigned srci = (unsigned)(bm * 64 + row) * LV_KP + chunk * 32 + kp;
            Aw0[row * AS_STRIDE + kp] = g_zhi[srci];
            Aw1[row * AS_STRIDE + kp] = g_zlo[srci];
        }
        // B: 32 k2 x 128 words (per term) = 4096 words
        #pragma unroll
        for (int i = 0; i < 8; i++) {
            int idx = tid + i * 512;
            int k2 = idx >> 7, nl = idx & 127;
            unsigned srci = (unsigned)(chunk * 32 + k2) * LV_NPAD + bn * 128 + nl;
            Bw0[k2 * BS_STRIDE + nl] = g_wlvh[srci];
            Bw1[k2 * BS_STRIDE + nl] = g_wlvl[srci];
        }
        __syncthreads();

        #pragma unroll
        for (int ks = 0; ks < 4; ks++) {
            unsigned a[2][4];
            unsigned b[4][2][2];
            const int cw = ks * 8 + tig;
            {
                int r0 = wm * 16 + gid;
                a[0][0] = Aw0[r0 * AS_STRIDE + cw];
                a[0][1] = Aw0[(r0 + 8) * AS_STRIDE + cw];
                a[0][2] = Aw0[r0 * AS_STRIDE + cw + 4];
                a[0][3] = Aw0[(r0 + 8) * AS_STRIDE + cw + 4];
                a[1][0] = Aw1[r0 * AS_STRIDE + cw];
                a[1][1] = Aw1[(r0 + 8) * AS_STRIDE + cw];
                a[1][2] = Aw1[r0 * AS_STRIDE + cw + 4];
                a[1][3] = Aw1[(r0 + 8) * AS_STRIDE + cw + 4];
            }
            #pragma unroll
            for (int nt = 0; nt < 4; nt++) {
                int n = wn * 32 + nt * 8 + gid;
                b[nt][0][0] = Bw0[cw * BS_STRIDE + n];
                b[nt][0][1] = Bw0[(cw + 4) * BS_STRIDE + n];
                b[nt][1][0] = Bw1[cw * BS_STRIDE + n];
                b[nt][1][1] = Bw1[(cw + 4) * BS_STRIDE + n];
            }
            #pragma unroll
            for (int nt = 0; nt < 4; nt++) {
                mma16816(acc[nt], a[0], b[nt][0]);
                mma16816(acc[nt], a[0], b[nt][1]);
                mma16816(acc[nt], a[1], b[nt][0]);
            }
        }
    }

    __syncthreads();
    float* Cs = (float*)smem;                    // [64][132]
    float* hq = (float*)(smem + 64 * BS_STRIDE * 4);  // [64][4]
    {
        int r0 = wm * 16 + gid;
        #pragma unroll
        for (int nt = 0; nt < 4; nt++) {
            int c = wn * 32 + nt * 8 + tig * 2;
            *(float2*)&Cs[r0 * BS_STRIDE + c]       = make_float2(acc[nt][0], acc[nt][1]);
            *(float2*)&Cs[(r0 + 8) * BS_STRIDE + c] = make_float2(acc[nt][2], acc[nt][3]);
        }
    }
    __syncthreads();

    {
        const int j    = tid & 127;
        const int rg   = tid >> 7;          // 0..3, 16 rows each
        const int qq   = (tid >> 5) & 3;    // j-quarter of this warp
        const int lane = tid & 31;
        const int n = bn * 128 + j;
        const bool valid = (n < T);
        const float bias = valid ? blv[n] : 0.f;

        #pragma unroll
        for (int rr = 0; rr < 16; rr++) {
            int r = rg * 16 + rr;
            float lv = fminf(fmaxf(Cs[r * BS_STRIDE + j] + bias, -9.f), -2.f);
            float h = valid ? lv : 0.f;
            if (valid) {
                int grow = bm * 64 + r;
                int set = grow >> 8, e = grow & 255;
                g_elv[set][e][n] = expf(lv);
                g_eml[set][e][n] = expf(-lv);
            }
            #pragma unroll
            for (int off = 16; off > 0; off >>= 1)
                h += __shfl_down_sync(0xffffffffu, h, off);
            if (lane == 0) hq[r * 4 + qq] = h;
        }
    }
    __syncthreads();
    if (tid < 64) {
        float s = hq[tid * 4] + hq[tid * 4 + 1] + hq[tid * 4 + 2] + hq[tid * 4 + 3];
        g_Hpart[bn][bm * 64 + tid] = s;
    }
}

// deterministic H reduction over the 9 N-tiles
__global__ void k_hsum()
{
    const int t = blockIdx.x * blockDim.x + threadIdx.x;
    if (t >= 512) return;
    float s = 0.5f * (float)T * LOG_2PIE;
    #pragma unroll
    for (int b = 0; b < 9; b++) s += g_Hpart[b][t];
    g_H[t >> 8][t & 255] = s;
}

// ============================================================
// K3: pairwise score (l2-l1 cancels between directions):
// score[i,j] = 0.5*sum_t[(e1+d^2)*q2 + (e2+d^2)*q1] - T + H1[i] + H2[j]
// ============================================================
__global__ void k_pair()
{
    __shared__ float sm1[16][CH + 1], se1[16][CH + 1], sq1[16][CH + 1];
    __shared__ float sm2[16][CH + 1], se2[16][CH + 1], sq2[16][CH + 1];
    const int tid = threadIdx.x;
    const int ty = tid >> 4, tx = tid & 15;
    const int i = blockIdx.y * 16 + ty;
    const int j = blockIdx.x * 16 + tx;

    float acc = 0.f;
    for (int c0 = 0; c0 < T; c0 += CH) {
        __syncthreads();
        for (int u = tid; u < 16 * CH; u += 256) {
            int rr = u / CH, t = u % CH;
            int tg = c0 + t;
            bool ok = tg < T;
            int ii = blockIdx.y * 16 + rr;
            int jj = blockIdx.x * 16 + rr;
            sm1[rr][t] = ok ? g_mu [0][ii][tg] : 0.f;
            se1[rr][t] = ok ? g_elv[0][ii][tg] : 0.f;
            sq1[rr][t] = ok ? g_eml[0][ii][tg] : 0.f;
            sm2[rr][t] = ok ? g_mu [1][jj][tg] : 0.f;
            se2[rr][t] = ok ? g_elv[1][jj][tg] : 0.f;
            sq2[rr][t] = ok ? g_eml[1][jj][tg] : 0.f;
        }
        __syncthreads();
        #pragma unroll 8
        for (int t = 0; t < CH; t++) {
            float m1 = sm1[ty][t], e1 = se1[ty][t], q1 = sq1[ty][t];
            float m2 = sm2[tx][t], e2 = se2[tx][t], q2 = sq2[tx][t];
            float d = m1 - m2;
            float dd = d * d;
            acc = fmaf(e1 + dd, q2, acc);
            acc = fmaf(e2 + dd, q1, acc);
        }
    }
    g_score[i][j] = 0.5f * acc - (float)T + g_H[0][i] + g_H[1][j];
}

// ============================================================
__global__ void k_softmax(float* __restrict__ out)
{
    const int i = blockIdx.x;
    const int j = threadIdx.x;
    __shared__ float red[256];
    float v = -g_score[i][j];
    red[j] = v;
    __syncthreads();
    for (int s = 128; s > 0; s >>= 1) {
        if (j < s) red[j] = fmaxf(red[j], red[j + s]);
        __syncthreads();
    }
    float mx = red[0];
    __syncthreads();
    float ex = expf(v - mx);
    red[j] = ex;
    __syncthreads();
    for (int s = 128; s > 0; s >>= 1) {
        if (j < s) red[j] += red[j + s];
        __syncthreads();
    }
    float lse = mx + logf(red[0]);
    out[(size_t)i * NEP + j] = v - lse;
}

__global__ void k_classes(float* __restrict__ out, int n)
{
    int k = blockIdx.x * blockDim.x + threadIdx.x;
    if (k < n) out[NEP * NEP + k] = (float)k;
}

// ============================================================
extern "C" void kernel_launch(void* const* d_in, const int* in_sizes, int n_in,
                              void* d_out, int out_size)
{
    const float* train_inputs  = (const float*)d_in[0];
    const float* train_targets = (const float*)d_in[1];
    const float* test_inputs   = (const float*)d_in[2];
    const float* test_targets  = (const float*)d_in[3];
    const float* W_fe          = (const float*)d_in[4];
    const float* b_fe          = (const float*)d_in[5];
    const float* W_lv          = (const float*)d_in[6];
    const float* b_lv          = (const float*)d_in[7];
    float* out = (float*)d_out;

    const int smem_fgemm = 2 * FG_BUF;           // 141312
    const int smem_lv    = 52224;
    cudaFuncSetAttribute(k_fgemm,  cudaFuncAttributeMaxDynamicSharedMemorySize, smem_fgemm);
    cudaFuncSetAttribute(k_lvgemm, cudaFuncAttributeMaxDynamicSharedMemorySize, smem_lv);

    k_split_in<<<dim3(8192, 1, 2), 256>>>(train_inputs, test_inputs);
    k_split_w<<<512, 256>>>(W_fe);
    k_split_wlv<<<2448, 256>>>(W_lv);
    k_targets<<<2, 256>>>(train_targets, test_targets);
    k_fgemm<<<dim3(4, 64, 2), 512, smem_fgemm>>>(b_fe);
    k_split_z<<<1088, 256>>>();
    k_lvgemm<<<dim3(9, 8), 512, smem_lv>>>(b_lv);
    k_hsum<<<2, 256>>>();
    k_pair<<<dim3(16, 16), 256>>>();
    k_softmax<<<NEP, 256>>>(out);

    int rem = out_size - NEP * NEP;
    if (rem > 0) {
        k_classes<<<(rem + 255) / 256, 256>>>(out, rem);
    }
}

// round 5
// speedup vs baseline: 3.4644x; 1.2397x over previous
#include <cuda_runtime.h>
#include <cuda_bf16.h>
#include <math.h>

#define NEP 256
#define NS  32
#define DIN 512
#define DF  512
#define T   1026
#define TT  513

#define LOG_2PIE 2.8378770664093453f

// K geometry for the logvar GEMM: K=1026 -> 513 k-pairs -> pad to 544 (17 chunks of 32)
#define LV_KP   544
#define LV_NPAD 1152   // 9 tiles of 128

// -------- device scratch (no allocations allowed) --------
__device__ float g_mu [2][NEP][T];   // z (mu)
__device__ float g_elv[2][NEP][T];   // exp(lv)
__device__ float g_eml[2][NEP][T];   // exp(-lv)
__device__ float g_Hpart[9][512];    // per-Ntile partial sums of lv per row (row = set*256+e)
__device__ float g_spart[8][NEP][NEP]; // pairwise score partials per t-slice

// bf16 split operands. Inputs: [set][8192 rows][256 k-pair words]
__device__ __align__(16) unsigned g_ihi[2][8192 * 256];
__device__ __align__(16) unsigned g_ilo[2][8192 * 256];
// W_fe split, k-pair interleaved
__device__ __align__(16) unsigned g_wphi[256 * 512];
__device__ __align__(16) unsigned g_wplo[256 * 512];
// z split: [512 rows (set*256+e)][544 k-pair words]
__device__ __align__(16) unsigned g_zhi[512 * LV_KP];
__device__ __align__(16) unsigned g_zlo[512 * LV_KP];
// W_lv split (padded)
__device__ __align__(16) unsigned g_wlvh[LV_KP * LV_NPAD];
__device__ __align__(16) unsigned g_wlvl[LV_KP * LV_NPAD];

// ============================================================
__device__ __forceinline__ void split1(float x, unsigned short& h, unsigned short& l)
{
    __nv_bfloat16 bh = __float2bfloat16(x);
    float r = x - __bfloat162float(bh);
    __nv_bfloat16 bl = __float2bfloat16(r);
    h = __bfloat16_as_ushort(bh);
    l = __bfloat16_as_ushort(bl);
}

__device__ __forceinline__ void cp16(unsigned saddr, const void* g)
{
    asm volatile("cp.async.cg.shared.global [%0], [%1], 16;\n" :: "r"(saddr), "l"(g));
}
__device__ __forceinline__ unsigned s2u(const void* p)
{
    return (unsigned)__cvta_generic_to_shared(p);
}

__global__ void k_split_in(const float* __restrict__ trin, const float* __restrict__ tein)
{
    const int set = blockIdx.z;
    const unsigned w = blockIdx.x * 256 + threadIdx.x;   // 2,097,152 words per set
    const float2* src = (const float2*)(set ? tein : trin);
    float2 v = src[w];
    unsigned short h0, l0, h1, l1;
    split1(v.x, h0, l0);
    split1(v.y, h1, l1);
    g_ihi[set][w] = (unsigned)h0 | ((unsigned)h1 << 16);
    g_ilo[set][w] = (unsigned)l0 | ((unsigned)l1 << 16);
}

// ============================================================
// merged prep: split W_fe (512 blocks) | split W_lv (2448 blocks) | targets (64 blocks)
// grid = 3024 blocks x 256 threads
// ============================================================
__global__ void k_prep(const float* __restrict__ Wfe, const float* __restrict__ Wlv,
                       const float* __restrict__ trtg, const float* __restrict__ tetg)
{
    const int b = blockIdx.x;
    const int tid = threadIdx.x;

    if (b < 512) {
        // ---- split W_fe ----
        const unsigned w = b * 256 + tid;              // 131072 words
        const int k2 = w >> 9;
        const int n  = w & 511;
        float x0 = Wfe[(size_t)(2 * k2) * DF + n];
        float x1 = Wfe[(size_t)(2 * k2 + 1) * DF + n];
        unsigned short h0, l0, h1, l1;
        split1(x0, h0, l0);
        split1(x1, h1, l1);
        g_wphi[w] = (unsigned)h0 | ((unsigned)h1 << 16);
        g_wplo[w] = (unsigned)l0 | ((unsigned)l1 << 16);
    } else if (b < 2960) {
        // ---- split W_lv (padded) ----
        const unsigned idx = (b - 512) * 256 + tid;    // up to 626688
        if (idx >= (unsigned)LV_KP * LV_NPAD) return;
        const int k2 = idx / LV_NPAD;
        const int n  = idx % LV_NPAD;
        const int k = 2 * k2;
        float x0 = (k     < T && n < T) ? Wlv[(size_t)k * T + n]       : 0.f;
        float x1 = (k + 1 < T && n < T) ? Wlv[(size_t)(k + 1) * T + n] : 0.f;
        unsigned short h0, l0, h1, l1;
        split1(x0, h0, l0);
        split1(x1, h1, l1);
        g_wlvh[idx] = (unsigned)h0 | ((unsigned)h1 << 16);
        g_wlvl[idx] = (unsigned)l0 | ((unsigned)l1 << 16);
    } else {
        // ---- targets: one warp per (set, episode) ----
        const int w = (b - 2960) * 8 + (tid >> 5);     // 0..511
        const int lane = tid & 31;
        const int set = w >> 8, e = w & 255;
        const float* tg = (set ? tetg : trtg) + (size_t)e * NS;
        float x = tg[lane];
        float s = x;
        #pragma unroll
        for (int off = 16; off > 0; off >>= 1) s += __shfl_xor_sync(0xffffffffu, s, off);
        float m = s * (1.f / NS);
        float d = x - m;
        float q = d * d;
        #pragma unroll
        for (int off = 16; off > 0; off >>= 1) q += __shfl_xor_sync(0xffffffffu, q, off);
        if (lane == 0) {
            g_mu[set][e][0]  = m;
            g_mu[set][e][TT] = sqrtf(q * (1.f / (NS - 1)));
        }
    }
}

__global__ void k_split_z()
{
    const unsigned idx = blockIdx.x * 256 + threadIdx.x;   // 512*544 = 278528
    if (idx >= 512u * LV_KP) return;
    const int row = idx / LV_KP;
    const int k2  = idx % LV_KP;
    const int set = row >> 8, e = row & 255;
    const int k = 2 * k2;
    float x0 = (k     < T) ? g_mu[set][e][k]     : 0.f;
    float x1 = (k + 1 < T) ? g_mu[set][e][k + 1] : 0.f;
    unsigned short h0, l0, h1, l1;
    split1(x0, h0, l0);
    split1(x1, h1, l1);
    g_zhi[idx] = (unsigned)h0 | ((unsigned)h1 << 16);
    g_zlo[idx] = (unsigned)l0 | ((unsigned)l1 << 16);
}

// ============================================================
// mma helper
// ============================================================
__device__ __forceinline__ void mma16816(float* d, const unsigned* a, const unsigned* b)
{
    asm volatile(
        "mma.sync.aligned.m16n8k16.row.col.f32.bf16.bf16.f32 "
        "{%0,%1,%2,%3}, {%4,%5,%6,%7}, {%8,%9}, {%0,%1,%2,%3};\n"
        : "+f"(d[0]), "+f"(d[1]), "+f"(d[2]), "+f"(d[3])
        : "r"(a[0]), "r"(a[1]), "r"(a[2]), "r"(a[3]), "r"(b[0]), "r"(b[1]));
}

#define AS_STRIDE 36   // uint32 words per A row (72 halves)
#define BS_STRIDE 132  // uint32 words per B k2-row / floats per C row

// ============================================================
// K1: tensor-core feature GEMM, cp.async double-buffered,
// fused bias/relu/mean/std epilogue. grid (4,64,2), 512 threads.
// ============================================================
#define FG_BUF 70656

__global__ __launch_bounds__(512, 1)
void k_fgemm(const float* __restrict__ bfe)
{
    extern __shared__ unsigned char smem[];
    const int ct  = blockIdx.x;
    const int eg  = blockIdx.y;
    const int set = blockIdx.z;
    const int tid = threadIdx.x;
    const int wid = tid >> 5;
    const int lid = tid & 31;
    const int wm  = wid >> 2;
    const int wn  = wid & 3;
    const int gid = lid >> 2;
    const int tig = lid & 3;

    const unsigned* gih = g_ihi[set];
    const unsigned* gil = g_ilo[set];

    float acc[2][4][4];
    #pragma unroll
    for (int mt = 0; mt < 2; mt++)
        #pragma unroll
        for (int nt = 0; nt < 4; nt++)
            #pragma unroll
            for (int r = 0; r < 4; r++) acc[mt][nt][r] = 0.f;

    auto stage = [&](int c, int buf) {
        unsigned* Aw0 = (unsigned*)(smem + buf * FG_BUF);
        unsigned* Aw1 = (unsigned*)(smem + buf * FG_BUF + 18432);
        unsigned* Bw0 = (unsigned*)(smem + buf * FG_BUF + 36864);
        unsigned* Bw1 = (unsigned*)(smem + buf * FG_BUF + 53760);
        #pragma unroll
        for (int i = 0; i < 2; i++) {
            int u = tid + i * 512;
            int row = u >> 3, kp = (u & 7) * 4;
            unsigned srci = (unsigned)(eg * 128 + row) * 256 + c * 32 + kp;
            cp16(s2u(&Aw0[row * AS_STRIDE + kp]), &gih[srci]);
            cp16(s2u(&Aw1[row * AS_STRIDE + kp]), &gil[srci]);
        }
        #pragma unroll
        for (int i = 0; i < 2; i++) {
            int u = tid + i * 512;
            int k2 = u >> 5, nl = (u & 31) * 4;
            unsigned srci = (unsigned)(c * 32 + k2) * 512 + ct * 128 + nl;
            cp16(s2u(&Bw0[k2 * BS_STRIDE + nl]), &g_wphi[srci]);
            cp16(s2u(&Bw1[k2 * BS_STRIDE + nl]), &g_wplo[srci]);
        }
        asm volatile("cp.async.commit_group;\n" ::: "memory");
    };

    stage(0, 0);

    for (int chunk = 0; chunk < 8; chunk++) {
        if (chunk < 7) {
            stage(chunk + 1, (chunk + 1) & 1);
            asm volatile("cp.async.wait_group 1;\n" ::: "memory");
        } else {
            asm volatile("cp.async.wait_group 0;\n" ::: "memory");
        }
        __syncthreads();

        const int buf = chunk & 1;
        unsigned* Aw0 = (unsigned*)(smem + buf * FG_BUF);
        unsigned* Aw1 = (unsigned*)(smem + buf * FG_BUF + 18432);
        unsigned* Bw0 = (unsigned*)(smem + buf * FG_BUF + 36864);
        unsigned* Bw1 = (unsigned*)(smem + buf * FG_BUF + 53760);

        #pragma unroll
        for (int ks = 0; ks < 4; ks++) {
            unsigned a[2][2][4];
            unsigned b[4][2][2];
            const int cw = ks * 8 + tig;
            #pragma unroll
            for (int mt = 0; mt < 2; mt++) {
                int r0 = wm * 32 + mt * 16 + gid;
                a[mt][0][0] = Aw0[r0 * AS_STRIDE + cw];
                a[mt][0][1] = Aw0[(r0 + 8) * AS_STRIDE + cw];
                a[mt][0][2] = Aw0[r0 * AS_STRIDE + cw + 4];
                a[mt][0][3] = Aw0[(r0 + 8) * AS_STRIDE + cw + 4];
                a[mt][1][0] = Aw1[r0 * AS_STRIDE + cw];
                a[mt][1][1] = Aw1[(r0 + 8) * AS_STRIDE + cw];
                a[mt][1][2] = Aw1[r0 * AS_STRIDE + cw + 4];
                a[mt][1][3] = Aw1[(r0 + 8) * AS_STRIDE + cw + 4];
            }
            #pragma unroll
            for (int nt = 0; nt < 4; nt++) {
                int n = wn * 32 + nt * 8 + gid;
                b[nt][0][0] = Bw0[cw * BS_STRIDE + n];
                b[nt][0][1] = Bw0[(cw + 4) * BS_STRIDE + n];
                b[nt][1][0] = Bw1[cw * BS_STRIDE + n];
                b[nt][1][1] = Bw1[(cw + 4) * BS_STRIDE + n];
            }
            #pragma unroll
            for (int mt = 0; mt < 2; mt++)
                #pragma unroll
                for (int nt = 0; nt < 4; nt++) {
                    mma16816(acc[mt][nt], a[mt][0], b[nt][0]);
                    mma16816(acc[mt][nt], a[mt][0], b[nt][1]);
                    mma16816(acc[mt][nt], a[mt][1], b[nt][0]);
                }
        }
        __syncthreads();
    }

    float* Cs = (float*)smem;
    #pragma unroll
    for (int mt = 0; mt < 2; mt++) {
        int r0 = wm * 32 + mt * 16 + gid;
        #pragma unroll
        for (int nt = 0; nt < 4; nt++) {
            int c = wn * 32 + nt * 8 + tig * 2;
            *(float2*)&Cs[r0 * BS_STRIDE + c]       = make_float2(acc[mt][nt][0], acc[mt][nt][1]);
            *(float2*)&Cs[(r0 + 8) * BS_STRIDE + c] = make_float2(acc[mt][nt][2], acc[mt][nt][3]);
        }
    }
    __syncthreads();

    {
        const int ep = tid >> 7;
        const int j  = tid & 127;
        const int f  = ct * 128 + j;
        const float bias = bfe[f];
        float s = 0.f, ss = 0.f;
        #pragma unroll
        for (int m = 0; m < NS; m++) {
            float v = Cs[(ep * 32 + m) * BS_STRIDE + j] + bias;
            v = fmaxf(v, 0.f);
            s += v;
            ss = fmaf(v, v, ss);
        }
        float mean = s * (1.f / NS);
        float var  = (ss - s * mean) * (1.f / (NS - 1));
        float stdv = sqrtf(fmaxf(var, 0.f));
        int e = eg * 4 + ep;
        g_mu[set][e][1 + f]      = mean;
        g_mu[set][e][TT + 1 + f] = stdv;
    }
}

// ============================================================
// K2: logvar GEMM on tensor cores. grid (9,8), 512 threads.
// Epilogue: +b_lv, clip, exp(+-lv), partial H into g_Hpart.
// ============================================================
__global__ __launch_bounds__(512, 1)
void k_lvgemm(const float* __restrict__ blv)
{
    extern __shared__ unsigned char smem[];
    unsigned* Aw0 = (unsigned*)(smem);
    unsigned* Aw1 = (unsigned*)(smem + 9216);
    unsigned* Bw0 = (unsigned*)(smem + 18432);
    unsigned* Bw1 = (unsigned*)(smem + 18432 + 16896);

    const int bn  = blockIdx.x;
    const int bm  = blockIdx.y;
    const int tid = threadIdx.x;
    const int wid = tid >> 5;
    const int lid = tid & 31;
    const int wm  = wid >> 2;
    const int wn  = wid & 3;
    const int gid = lid >> 2;
    const int tig = lid & 3;

    float acc[4][4];
    #pragma unroll
    for (int nt = 0; nt < 4; nt++)
        #pragma unroll
        for (int r = 0; r < 4; r++) acc[nt][r] = 0.f;

    for (int chunk = 0; chunk < 17; chunk++) {
        __syncthreads();
        #pragma unroll
        for (int i = 0; i < 4; i++) {
            int idx = tid + i * 512;
            int row = idx >> 5, kp = idx & 31;
            unsigned srci = (unsigned)(bm * 64 + row) * LV_KP + chunk * 32 + kp;
            Aw0[row * AS_STRIDE + kp] = g_zhi[srci];
            Aw1[row * AS_STRIDE + kp] = g_zlo[srci];
        }
        #pragma unroll
        for (int i = 0; i < 8; i++) {
            int idx = tid + i * 512;
            int k2 = idx >> 7, nl = idx & 127;
            unsigned srci = (unsigned)(chunk * 32 + k2) * LV_NPAD + bn * 128 + nl;
            Bw0[k2 * BS_STRIDE + nl] = g_wlvh[srci];
            Bw1[k2 * BS_STRIDE + nl] = g_wlvl[srci];
        }
        __syncthreads();

        #pragma unroll
        for (int ks = 0; ks < 4; ks++) {
            unsigned a[2][4];
            unsigned b[4][2][2];
            const int cw = ks * 8 + tig;
            {
                int r0 = wm * 16 + gid;
                a[0][0] = Aw0[r0 * AS_STRIDE + cw];
                a[0][1] = Aw0[(r0 + 8) * AS_STRIDE + cw];
                a[0][2] = Aw0[r0 * AS_STRIDE + cw + 4];
                a[0][3] = Aw0[(r0 + 8) * AS_STRIDE + cw + 4];
                a[1][0] = Aw1[r0 * AS_STRIDE + cw];
                a[1][1] = Aw1[(r0 + 8) * AS_STRIDE + cw];
                a[1][2] = Aw1[r0 * AS_STRIDE + cw + 4];
                a[1][3] = Aw1[(r0 + 8) * AS_STRIDE + cw + 4];
            }
            #pragma unroll
            for (int nt = 0; nt < 4; nt++) {
                int n = wn * 32 + nt * 8 + gid;
                b[nt][0][0] = Bw0[cw * BS_STRIDE + n];
                b[nt][0][1] = Bw0[(cw + 4) * BS_STRIDE + n];
                b[nt][1][0] = Bw1[cw * BS_STRIDE + n];
                b[nt][1][1] = Bw1[(cw + 4) * BS_STRIDE + n];
            }
            #pragma unroll
            for (int nt = 0; nt < 4; nt++) {
                mma16816(acc[nt], a[0], b[nt][0]);
                mma16816(acc[nt], a[0], b[nt][1]);
                mma16816(acc[nt], a[1], b[nt][0]);
            }
        }
    }

    __syncthreads();
    float* Cs = (float*)smem;                         // [64][132]
    float* hq = (float*)(smem + 64 * BS_STRIDE * 4);  // [64][4]
    {
        int r0 = wm * 16 + gid;
        #pragma unroll
        for (int nt = 0; nt < 4; nt++) {
            int c = wn * 32 + nt * 8 + tig * 2;
            *(float2*)&Cs[r0 * BS_STRIDE + c]       = make_float2(acc[nt][0], acc[nt][1]);
            *(float2*)&Cs[(r0 + 8) * BS_STRIDE + c] = make_float2(acc[nt][2], acc[nt][3]);
        }
    }
    __syncthreads();

    {
        const int j    = tid & 127;
        const int rg   = tid >> 7;
        const int qq   = (tid >> 5) & 3;
        const int lane = tid & 31;
        const int n = bn * 128 + j;
        const bool valid = (n < T);
        const float bias = valid ? blv[n] : 0.f;

        #pragma unroll
        for (int rr = 0; rr < 16; rr++) {
            int r = rg * 16 + rr;
            float lv = fminf(fmaxf(Cs[r * BS_STRIDE + j] + bias, -9.f), -2.f);
            float h = valid ? lv : 0.f;
            if (valid) {
                int grow = bm * 64 + r;
                int set = grow >> 8, e = grow & 255;
                g_elv[set][e][n] = expf(lv);
                g_eml[set][e][n] = expf(-lv);
            }
            #pragma unroll
            for (int off = 16; off > 0; off >>= 1)
                h += __shfl_down_sync(0xffffffffu, h, off);
            if (lane == 0) hq[r * 4 + qq] = h;
        }
    }
    __syncthreads();
    if (tid < 64) {
        float s = hq[tid * 4] + hq[tid * 4 + 1] + hq[tid * 4 + 2] + hq[tid * 4 + 3];
        g_Hpart[bn][bm * 64 + tid] = s;
    }
}

// ============================================================
// K3: pairwise score partials, register-tiled 4x4, t-sliced.
// tile 64x64 per block, 256 threads (16x16), each thread 4x4 outputs.
// grid (4, 4, 8): z = t-slice of 129 values.
// partial[i,j] = sum_t (e1+d^2)*q2 + (e2+d^2)*q1
// ============================================================
__global__ __launch_bounds__(256)
void k_pairp()
{
    __shared__ float s1m[64][17], s1e[64][17], s1q[64][17];
    __shared__ float s2m[64][17], s2e[64][17], s2q[64][17];
    const int tid = threadIdx.x;
    const int ty = tid >> 4, tx = tid & 15;
    const int i0 = blockIdx.y * 64;
    const int j0 = blockIdx.x * 64;
    const int bz = blockIdx.z;
    const int t_beg = bz * 129;
    const int t_end = min(T, t_beg + 129);

    float acc[4][4];
    #pragma unroll
    for (int a = 0; a < 4; a++)
        #pragma unroll
        for (int b = 0; b < 4; b++) acc[a][b] = 0.f;

    for (int c0 = t_beg; c0 < t_end; c0 += 16) {
        __syncthreads();
        #pragma unroll
        for (int u4 = 0; u4 < 4; u4++) {
            int u = tid + u4 * 256;          // 0..1023
            int row = u >> 4, tt = u & 15;
            int tg = c0 + tt;
            bool ok = tg < t_end;
            int tga = ok ? tg : 0;
            float m1 = g_mu [0][i0 + row][tga];
            float e1 = g_elv[0][i0 + row][tga];
            float q1 = g_eml[0][i0 + row][tga];
            float m2 = g_mu [1][j0 + row][tga];
            float e2 = g_elv[1][j0 + row][tga];
            float q2 = g_eml[1][j0 + row][tga];
            s1m[row][tt] = ok ? m1 : 0.f;
            s1e[row][tt] = ok ? e1 : 0.f;
            s1q[row][tt] = ok ? q1 : 0.f;   // q=0 pad kills both directions
            s2m[row][tt] = ok ? m2 : 0.f;
            s2e[row][tt] = ok ? e2 : 0.f;
            s2q[row][tt] = ok ? q2 : 0.f;
        }
        __syncthreads();

        #pragma unroll
        for (int tt = 0; tt < 16; tt++) {
            float m1[4], e1[4], q1[4], m2[4], e2[4], q2[4];
            #pragma unroll
            for (int a = 0; a < 4; a++) {
                int r = ty + 16 * a;
                m1[a] = s1m[r][tt];
                e1[a] = s1e[r][tt];
                q1[a] = s1q[r][tt];
            }
            #pragma unroll
            for (int b = 0; b < 4; b++) {
                int r = tx + 16 * b;
                m2[b] = s2m[r][tt];
                e2[b] = s2e[r][tt];
                q2[b] = s2q[r][tt];
            }
            #pragma unroll
            for (int a = 0; a < 4; a++)
                #pragma unroll
                for (int b = 0; b < 4; b++) {
                    float d  = m1[a] - m2[b];
                    float dd = d * d;
                    acc[a][b] = fmaf(e1[a] + dd, q2[b], acc[a][b]);
                    acc[a][b] = fmaf(e2[b] + dd, q1[a], acc[a][b]);
                }
        }
    }

    #pragma unroll
    for (int a = 0; a < 4; a++) {
        int i = i0 + ty + 16 * a;
        #pragma unroll
        for (int b = 0; b < 4; b++) {
            int j = j0 + tx + 16 * b;
            g_spart[bz][i][j] = acc[a][b];
        }
    }
}

// ============================================================
// K4: assemble score + log_softmax + classes tail.
// score[i,j] = 0.5*sum_z spart - T + H0[i] + H1[j],  H = sum Hpart + 0.5*T*log2pie
// ============================================================
__global__ void k_softmax(float* __restrict__ out, int out_size)
{
    const int i = blockIdx.x;
    const int j = threadIdx.x;
    __shared__ float red[256];

    float s = 0.f;
    #pragma unroll
    for (int z = 0; z < 8; z++) s += g_spart[z][i][j];

    float H0 = 0.5f * (float)T * LOG_2PIE;
    float H1 = H0;
    #pragma unroll
    for (int b = 0; b < 9; b++) {
        H0 += g_Hpart[b][i];
        H1 += g_Hpart[b][NEP + j];
    }
    float score = 0.5f * s - (float)T + H0 + H1;
    float v = -score;

    red[j] = v;
    __syncthreads();
    for (int st = 128; st > 0; st >>= 1) {
        if (j < st) red[j] = fmaxf(red[j], red[j + st]);
        __syncthreads();
    }
    float mx = red[0];
    __syncthreads();
    float ex = expf(v - mx);
    red[j] = ex;
    __syncthreads();
    for (int st = 128; st > 0; st >>= 1) {
        if (j < st) red[j] += red[j + st];
        __syncthreads();
    }
    float lse = mx + logf(red[0]);
    out[(size_t)i * NEP + j] = v - lse;

    if (j == 0 && NEP * NEP + i < out_size)
        out[NEP * NEP + i] = (float)i;
}

// ============================================================
extern "C" void kernel_launch(void* const* d_in, const int* in_sizes, int n_in,
                              void* d_out, int out_size)
{
    const float* train_inputs  = (const float*)d_in[0];
    const float* train_targets = (const float*)d_in[1];
    const float* test_inputs   = (const float*)d_in[2];
    const float* test_targets  = (const float*)d_in[3];
    const float* W_fe          = (const float*)d_in[4];
    const float* b_fe          = (const float*)d_in[5];
    const float* W_lv          = (const float*)d_in[6];
    const float* b_lv          = (const float*)d_in[7];
    float* out = (float*)d_out;

    const int smem_fgemm = 2 * FG_BUF;           // 141312
    const int smem_lv    = 52224;
    cudaFuncSetAttribute(k_fgemm,  cudaFuncAttributeMaxDynamicSharedMemorySize, smem_fgemm);
    cudaFuncSetAttribute(k_lvgemm, cudaFuncAttributeMaxDynamicSharedMemorySize, smem_lv);

    k_split_in<<<dim3(8192, 1, 2), 256>>>(train_inputs, test_inputs);
    k_prep<<<3024, 256>>>(W_fe, W_lv, train_targets, test_targets);
    k_fgemm<<<dim3(4, 64, 2), 512, smem_fgemm>>>(b_fe);
    k_split_z<<<1088, 256>>>();
    k_lvgemm<<<dim3(9, 8), 512, smem_lv>>>(b_lv);
    k_pairp<<<dim3(4, 4, 8), 256>>>();
    k_softmax<<<NEP, 256>>>(out, out_size);
}

// round 6
// speedup vs baseline: 3.7857x; 1.0927x over previous
#include <cuda_runtime.h>
#include <cuda_bf16.h>
#include <math.h>

#define NEP 256
#define NS  32
#define DIN 512
#define DF  512
#define T   1026
#define TT  513

#define LOG_2PIE 2.8378770664093453f

// K geometry for the logvar GEMM: K=1026 -> 513 k-pairs -> pad to 544 (17 chunks of 32)
#define LV_KP   544
#define LV_NPAD 1152   // 9 tiles of 128

// -------- device scratch (no allocations allowed) --------
__device__ float g_mu [2][NEP][T];   // z (mu)
__device__ float g_elv[2][NEP][T];   // exp(lv)
__device__ float g_eml[2][NEP][T];   // exp(-lv)
__device__ float g_Hpart[9][512];    // per-Ntile partial sums of lv per row (row = set*256+e)
__device__ float g_spart[8][NEP][NEP]; // pairwise score partials per t-slice

// bf16 split operands. Inputs: [set][8192 rows][256 k-pair words]
__device__ __align__(16) unsigned g_ihi[2][8192 * 256];
__device__ __align__(16) unsigned g_ilo[2][8192 * 256];
// W_fe split, k-pair interleaved
__device__ __align__(16) unsigned g_wphi[256 * 512];
__device__ __align__(16) unsigned g_wplo[256 * 512];
// z split: [512 rows (set*256+e)][544 k-pair words]
__device__ __align__(16) unsigned g_zhi[512 * LV_KP];
__device__ __align__(16) unsigned g_zlo[512 * LV_KP];
// W_lv split (padded)
__device__ __align__(16) unsigned g_wlvh[LV_KP * LV_NPAD];
__device__ __align__(16) unsigned g_wlvl[LV_KP * LV_NPAD];

// ============================================================
__device__ __forceinline__ void split1(float x, unsigned short& h, unsigned short& l)
{
    __nv_bfloat16 bh = __float2bfloat16(x);
    float r = x - __bfloat162float(bh);
    __nv_bfloat16 bl = __float2bfloat16(r);
    h = __bfloat16_as_ushort(bh);
    l = __bfloat16_as_ushort(bl);
}

__device__ __forceinline__ void cp16(unsigned saddr, const void* g)
{
    asm volatile("cp.async.cg.shared.global [%0], [%1], 16;\n" :: "r"(saddr), "l"(g));
}
__device__ __forceinline__ unsigned s2u(const void* p)
{
    return (unsigned)__cvta_generic_to_shared(p);
}

// ============================================================
// merged prep: split inputs (16384) | W_fe (512) | W_lv (2448) | targets (64)
// grid = 19408 blocks x 256 threads
// ============================================================
__global__ void k_prep(const float* __restrict__ trin, const float* __restrict__ tein,
                       const float* __restrict__ Wfe, const float* __restrict__ Wlv,
                       const float* __restrict__ trtg, const float* __restrict__ tetg)
{
    const int b = blockIdx.x;
    const int tid = threadIdx.x;

    if (b < 16384) {
        // ---- split inputs ----
        const int set = b >> 13;
        const unsigned w = (unsigned)(b & 8191) * 256 + tid;   // 2,097,152 words per set
        const float2* src = (const float2*)(set ? tein : trin);
        float2 v = src[w];
        unsigned short h0, l0, h1, l1;
        split1(v.x, h0, l0);
        split1(v.y, h1, l1);
        g_ihi[set][w] = (unsigned)h0 | ((unsigned)h1 << 16);
        g_ilo[set][w] = (unsigned)l0 | ((unsigned)l1 << 16);
    } else if (b < 16896) {
        // ---- split W_fe ----
        const unsigned w = (b - 16384) * 256 + tid;            // 131072 words
        const int k2 = w >> 9;
        const int n  = w & 511;
        float x0 = Wfe[(size_t)(2 * k2) * DF + n];
        float x1 = Wfe[(size_t)(2 * k2 + 1) * DF + n];
        unsigned short h0, l0, h1, l1;
        split1(x0, h0, l0);
        split1(x1, h1, l1);
        g_wphi[w] = (unsigned)h0 | ((unsigned)h1 << 16);
        g_wplo[w] = (unsigned)l0 | ((unsigned)l1 << 16);
    } else if (b < 19344) {
        // ---- split W_lv (padded) ----
        const unsigned idx = (b - 16896) * 256 + tid;          // up to 626688
        if (idx >= (unsigned)LV_KP * LV_NPAD) return;
        const int k2 = idx / LV_NPAD;
        const int n  = idx % LV_NPAD;
        const int k = 2 * k2;
        float x0 = (k     < T && n < T) ? Wlv[(size_t)k * T + n]       : 0.f;
        float x1 = (k + 1 < T && n < T) ? Wlv[(size_t)(k + 1) * T + n] : 0.f;
        unsigned short h0, l0, h1, l1;
        split1(x0, h0, l0);
        split1(x1, h1, l1);
        g_wlvh[idx] = (unsigned)h0 | ((unsigned)h1 << 16);
        g_wlvl[idx] = (unsigned)l0 | ((unsigned)l1 << 16);
    } else {
        // ---- targets: one warp per (set, episode) ----
        const int w = (b - 19344) * 8 + (tid >> 5);            // 0..511
        const int lane = tid & 31;
        const int set = w >> 8, e = w & 255;
        const float* tg = (set ? tetg : trtg) + (size_t)e * NS;
        float x = tg[lane];
        float s = x;
        #pragma unroll
        for (int off = 16; off > 0; off >>= 1) s += __shfl_xor_sync(0xffffffffu, s, off);
        float m = s * (1.f / NS);
        float d = x - m;
        float q = d * d;
        #pragma unroll
        for (int off = 16; off > 0; off >>= 1) q += __shfl_xor_sync(0xffffffffu, q, off);
        if (lane == 0) {
            g_mu[set][e][0]  = m;
            g_mu[set][e][TT] = sqrtf(q * (1.f / (NS - 1)));
        }
    }
}

__global__ void k_split_z()
{
    const unsigned idx = blockIdx.x * 256 + threadIdx.x;   // 512*544 = 278528
    if (idx >= 512u * LV_KP) return;
    const int row = idx / LV_KP;
    const int k2  = idx % LV_KP;
    const int set = row >> 8, e = row & 255;
    const int k = 2 * k2;
    float x0 = (k     < T) ? g_mu[set][e][k]     : 0.f;
    float x1 = (k + 1 < T) ? g_mu[set][e][k + 1] : 0.f;
    unsigned short h0, l0, h1, l1;
    split1(x0, h0, l0);
    split1(x1, h1, l1);
    g_zhi[idx] = (unsigned)h0 | ((unsigned)h1 << 16);
    g_zlo[idx] = (unsigned)l0 | ((unsigned)l1 << 16);
}

// ============================================================
// mma helper
// ============================================================
__device__ __forceinline__ void mma16816(float* d, const unsigned* a, const unsigned* b)
{
    asm volatile(
        "mma.sync.aligned.m16n8k16.row.col.f32.bf16.bf16.f32 "
        "{%0,%1,%2,%3}, {%4,%5,%6,%7}, {%8,%9}, {%0,%1,%2,%3};\n"
        : "+f"(d[0]), "+f"(d[1]), "+f"(d[2]), "+f"(d[3])
        : "r"(a[0]), "r"(a[1]), "r"(a[2]), "r"(a[3]), "r"(b[0]), "r"(b[1]));
}

#define AS_STRIDE 36   // uint32 words per A row (72 halves)
#define BS_STRIDE 132  // uint32 words per B k2-row / floats per C row

// ============================================================
// K1: tensor-core feature GEMM, cp.async double-buffered.
// Block 128x128, 256 threads (8 warps, 2x4 grid of 64x32 warp tiles).
// Fused bias/relu/mean/std epilogue. grid (4,64,2).
// ============================================================
#define FG_BUF 70656

__global__ __launch_bounds__(256, 1)
void k_fgemm(const float* __restrict__ bfe)
{
    extern __shared__ unsigned char smem[];
    const int ct  = blockIdx.x;
    const int eg  = blockIdx.y;
    const int set = blockIdx.z;
    const int tid = threadIdx.x;
    const int wid = tid >> 5;
    const int lid = tid & 31;
    const int wm  = wid >> 2;        // 0..1 : 64-row warp tile
    const int wn  = wid & 3;         // 0..3 : 32-col warp tile
    const int gid = lid >> 2;
    const int tig = lid & 3;

    const unsigned* gih = g_ihi[set];
    const unsigned* gil = g_ilo[set];

    float acc[4][4][4];
    #pragma unroll
    for (int mt = 0; mt < 4; mt++)
        #pragma unroll
        for (int nt = 0; nt < 4; nt++)
            #pragma unroll
            for (int r = 0; r < 4; r++) acc[mt][nt][r] = 0.f;

    auto stage = [&](int c, int buf) {
        unsigned* Aw0 = (unsigned*)(smem + buf * FG_BUF);
        unsigned* Aw1 = (unsigned*)(smem + buf * FG_BUF + 18432);
        unsigned* Bw0 = (unsigned*)(smem + buf * FG_BUF + 36864);
        unsigned* Bw1 = (unsigned*)(smem + buf * FG_BUF + 53760);
        #pragma unroll
        for (int i = 0; i < 4; i++) {
            int u = tid + i * 256;                 // 1024 16B units per term
            int row = u >> 3, kp = (u & 7) * 4;
            unsigned srci = (unsigned)(eg * 128 + row) * 256 + c * 32 + kp;
            cp16(s2u(&Aw0[row * AS_STRIDE + kp]), &gih[srci]);
            cp16(s2u(&Aw1[row * AS_STRIDE + kp]), &gil[srci]);
        }
        #pragma unroll
        for (int i = 0; i < 4; i++) {
            int u = tid + i * 256;
            int k2 = u >> 5, nl = (u & 31) * 4;
            unsigned srci = (unsigned)(c * 32 + k2) * 512 + ct * 128 + nl;
            cp16(s2u(&Bw0[k2 * BS_STRIDE + nl]), &g_wphi[srci]);
            cp16(s2u(&Bw1[k2 * BS_STRIDE + nl]), &g_wplo[srci]);
        }
        asm volatile("cp.async.commit_group;\n" ::: "memory");
    };

    stage(0, 0);

    for (int chunk = 0; chunk < 8; chunk++) {
        if (chunk < 7) {
            stage(chunk + 1, (chunk + 1) & 1);
            asm volatile("cp.async.wait_group 1;\n" ::: "memory");
        } else {
            asm volatile("cp.async.wait_group 0;\n" ::: "memory");
        }
        __syncthreads();

        const int buf = chunk & 1;
        unsigned* Aw0 = (unsigned*)(smem + buf * FG_BUF);
        unsigned* Aw1 = (unsigned*)(smem + buf * FG_BUF + 18432);
        unsigned* Bw0 = (unsigned*)(smem + buf * FG_BUF + 36864);
        unsigned* Bw1 = (unsigned*)(smem + buf * FG_BUF + 53760);

        #pragma unroll
        for (int ks = 0; ks < 4; ks++) {
            const int cw = ks * 8 + tig;
            unsigned b[4][2][2];
            #pragma unroll
            for (int nt = 0; nt < 4; nt++) {
                int n = wn * 32 + nt * 8 + gid;
                b[nt][0][0] = Bw0[cw * BS_STRIDE + n];
                b[nt][0][1] = Bw0[(cw + 4) * BS_STRIDE + n];
                b[nt][1][0] = Bw1[cw * BS_STRIDE + n];
                b[nt][1][1] = Bw1[(cw + 4) * BS_STRIDE + n];
            }
            #pragma unroll
            for (int mt = 0; mt < 4; mt++) {
                unsigned a[2][4];
                int r0 = wm * 64 + mt * 16 + gid;
                a[0][0] = Aw0[r0 * AS_STRIDE + cw];
                a[0][1] = Aw0[(r0 + 8) * AS_STRIDE + cw];
                a[0][2] = Aw0[r0 * AS_STRIDE + cw + 4];
                a[0][3] = Aw0[(r0 + 8) * AS_STRIDE + cw + 4];
                a[1][0] = Aw1[r0 * AS_STRIDE + cw];
                a[1][1] = Aw1[(r0 + 8) * AS_STRIDE + cw];
                a[1][2] = Aw1[r0 * AS_STRIDE + cw + 4];
                a[1][3] = Aw1[(r0 + 8) * AS_STRIDE + cw + 4];
                #pragma unroll
                for (int nt = 0; nt < 4; nt++) {
                    mma16816(acc[mt][nt], a[0], b[nt][0]);
                    mma16816(acc[mt][nt], a[0], b[nt][1]);
                    mma16816(acc[mt][nt], a[1], b[nt][0]);
                }
            }
        }
        __syncthreads();
    }

    float* Cs = (float*)smem;     // [128][132]
    #pragma unroll
    for (int mt = 0; mt < 4; mt++) {
        int r0 = wm * 64 + mt * 16 + gid;
        #pragma unroll
        for (int nt = 0; nt < 4; nt++) {
            int c = wn * 32 + nt * 8 + tig * 2;
            *(float2*)&Cs[r0 * BS_STRIDE + c]       = make_float2(acc[mt][nt][0], acc[mt][nt][1]);
            *(float2*)&Cs[(r0 + 8) * BS_STRIDE + c] = make_float2(acc[mt][nt][2], acc[mt][nt][3]);
        }
    }
    __syncthreads();

    {
        const int j  = tid & 127;
        const int f  = ct * 128 + j;
        const float bias = bfe[f];
        #pragma unroll
        for (int half = 0; half < 2; half++) {
            const int ep = (tid >> 7) * 2 + half;   // 0..3
            float s = 0.f, ss = 0.f;
            #pragma unroll
            for (int m = 0; m < NS; m++) {
                float v = Cs[(ep * 32 + m) * BS_STRIDE + j] + bias;
                v = fmaxf(v, 0.f);
                s += v;
                ss = fmaf(v, v, ss);
            }
            float mean = s * (1.f / NS);
            float var  = (ss - s * mean) * (1.f / (NS - 1));
            float stdv = sqrtf(fmaxf(var, 0.f));
            int e = eg * 4 + ep;
            g_mu[set][e][1 + f]      = mean;
            g_mu[set][e][TT + 1 + f] = stdv;
        }
    }
}

// ============================================================
// K2: logvar GEMM on tensor cores, cp.async double-buffered.
// grid (9,8), 512 threads, block 64x128 (warp 16x32).
// Epilogue: +b_lv, clip, exp(+-lv), partial H into g_Hpart.
// ============================================================
#define LV_BUF 52224

__global__ __launch_bounds__(512, 1)
void k_lvgemm(const float* __restrict__ blv)
{
    extern __shared__ unsigned char smem[];

    const int bn  = blockIdx.x;
    const int bm  = blockIdx.y;
    const int tid = threadIdx.x;
    const int wid = tid >> 5;
    const int lid = tid & 31;
    const int wm  = wid >> 2;
    const int wn  = wid & 3;
    const int gid = lid >> 2;
    const int tig = lid & 3;

    float acc[4][4];
    #pragma unroll
    for (int nt = 0; nt < 4; nt++)
        #pragma unroll
        for (int r = 0; r < 4; r++) acc[nt][r] = 0.f;

    auto stage = [&](int c, int buf) {
        unsigned* Aw0 = (unsigned*)(smem + buf * LV_BUF);
        unsigned* Aw1 = (unsigned*)(smem + buf * LV_BUF + 9216);
        unsigned* Bw0 = (unsigned*)(smem + buf * LV_BUF + 18432);
        unsigned* Bw1 = (unsigned*)(smem + buf * LV_BUF + 35328);
        {
            int u = tid;                            // 512 units per term (64 rows x 8)
            int row = u >> 3, kp = (u & 7) * 4;
            unsigned srci = (unsigned)(bm * 64 + row) * LV_KP + c * 32 + kp;
            cp16(s2u(&Aw0[row * AS_STRIDE + kp]), &g_zhi[srci]);
            cp16(s2u(&Aw1[row * AS_STRIDE + kp]), &g_zlo[srci]);
        }
        #pragma unroll
        for (int i = 0; i < 2; i++) {
            int u = tid + i * 512;                  // 1024 units per term
            int k2 = u >> 5, nl = (u & 31) * 4;
            unsigned srci = (unsigned)(c * 32 + k2) * LV_NPAD + bn * 128 + nl;
            cp16(s2u(&Bw0[k2 * BS_STRIDE + nl]), &g_wlvh[srci]);
            cp16(s2u(&Bw1[k2 * BS_STRIDE + nl]), &g_wlvl[srci]);
        }
        asm volatile("cp.async.commit_group;\n" ::: "memory");
    };

    stage(0, 0);

    for (int chunk = 0; chunk < 17; chunk++) {
        if (chunk < 16) {
            stage(chunk + 1, (chunk + 1) & 1);
            asm volatile("cp.async.wait_group 1;\n" ::: "memory");
        } else {
            asm volatile("cp.async.wait_group 0;\n" ::: "memory");
        }
        __syncthreads();

        const int buf = chunk & 1;
        unsigned* Aw0 = (unsigned*)(smem + buf * LV_BUF);
        unsigned* Aw1 = (unsigned*)(smem + buf * LV_BUF + 9216);
        unsigned* Bw0 = (unsigned*)(smem + buf * LV_BUF + 18432);
        unsigned* Bw1 = (unsigned*)(smem + buf * LV_BUF + 35328);

        #pragma unroll
        for (int ks = 0; ks < 4; ks++) {
            unsigned a[2][4];
            unsigned b[4][2][2];
            const int cw = ks * 8 + tig;
            {
                int r0 = wm * 16 + gid;
                a[0][0] = Aw0[r0 * AS_STRIDE + cw];
                a[0][1] = Aw0[(r0 + 8) * AS_STRIDE + cw];
                a[0][2] = Aw0[r0 * AS_STRIDE + cw + 4];
                a[0][3] = Aw0[(r0 + 8) * AS_STRIDE + cw + 4];
                a[1][0] = Aw1[r0 * AS_STRIDE + cw];
                a[1][1] = Aw1[(r0 + 8) * AS_STRIDE + cw];
                a[1][2] = Aw1[r0 * AS_STRIDE + cw + 4];
                a[1][3] = Aw1[(r0 + 8) * AS_STRIDE + cw + 4];
            }
            #pragma unroll
            for (int nt = 0; nt < 4; nt++) {
                int n = wn * 32 + nt * 8 + gid;
                b[nt][0][0] = Bw0[cw * BS_STRIDE + n];
                b[nt][0][1] = Bw0[(cw + 4) * BS_STRIDE + n];
                b[nt][1][0] = Bw1[cw * BS_STRIDE + n];
                b[nt][1][1] = Bw1[(cw + 4) * BS_STRIDE + n];
            }
            #pragma unroll
            for (int nt = 0; nt < 4; nt++) {
                mma16816(acc[nt], a[0], b[nt][0]);
                mma16816(acc[nt], a[0], b[nt][1]);
                mma16816(acc[nt], a[1], b[nt][0]);
            }
        }
        __syncthreads();
    }

    float* Cs = (float*)smem;                         // [64][132]
    float* hq = (float*)(smem + 64 * BS_STRIDE * 4);  // [64][4]
    {
        int r0 = wm * 16 + gid;
        #pragma unroll
        for (int nt = 0; nt < 4; nt++) {
            int c = wn * 32 + nt * 8 + tig * 2;
            *(float2*)&Cs[r0 * BS_STRIDE + c]       = make_float2(acc[nt][0], acc[nt][1]);
            *(float2*)&Cs[(r0 + 8) * BS_STRIDE + c] = make_float2(acc[nt][2], acc[nt][3]);
        }
    }
    __syncthreads();

    {
        const int j    = tid & 127;
        const int rg   = tid >> 7;
        const int qq   = (tid >> 5) & 3;
        const int lane = tid & 31;
        const int n = bn * 128 + j;
        const bool valid = (n < T);
        const float bias = valid ? blv[n] : 0.f;

        #pragma unroll
        for (int rr = 0; rr < 16; rr++) {
            int r = rg * 16 + rr;
            float lv = fminf(fmaxf(Cs[r * BS_STRIDE + j] + bias, -9.f), -2.f);
            float h = valid ? lv : 0.f;
            if (valid) {
                int grow = bm * 64 + r;
                int set = grow >> 8, e = grow & 255;
                g_elv[set][e][n] = expf(lv);
                g_eml[set][e][n] = expf(-lv);
            }
            #pragma unroll
            for (int off = 16; off > 0; off >>= 1)
                h += __shfl_down_sync(0xffffffffu, h, off);
            if (lane == 0) hq[r * 4 + qq] = h;
        }
    }
    __syncthreads();
    if (tid < 64) {
        float s = hq[tid * 4] + hq[tid * 4 + 1] + hq[tid * 4 + 2] + hq[tid * 4 + 3];
        g_Hpart[bn][bm * 64 + tid] = s;
    }
}

// ============================================================
// K3: pairwise score partials, register-tiled 4x4, t-sliced.
// ============================================================
__global__ __launch_bounds__(256)
void k_pairp()
{
    __shared__ float s1m[64][17], s1e[64][17], s1q[64][17];
    __shared__ float s2m[64][17], s2e[64][17], s2q[64][17];
    const int tid = threadIdx.x;
    const int ty = tid >> 4, tx = tid & 15;
    const int i0 = blockIdx.y * 64;
    const int j0 = blockIdx.x * 64;
    const int bz = blockIdx.z;
    const int t_beg = bz * 129;
    const int t_end = min(T, t_beg + 129);

    float acc[4][4];
    #pragma unroll
    for (int a = 0; a < 4; a++)
        #pragma unroll
        for (int b = 0; b < 4; b++) acc[a][b] = 0.f;

    for (int c0 = t_beg; c0 < t_end; c0 += 16) {
        __syncthreads();
        #pragma unroll
        for (int u4 = 0; u4 < 4; u4++) {
            int u = tid + u4 * 256;
            int row = u >> 4, tt = u & 15;
            int tg = c0 + tt;
            bool ok = tg < t_end;
            int tga = ok ? tg : 0;
            float m1 = g_mu [0][i0 + row][tga];
            float e1 = g_elv[0][i0 + row][tga];
            float q1 = g_eml[0][i0 + row][tga];
            float m2 = g_mu [1][j0 + row][tga];
            float e2 = g_elv[1][j0 + row][tga];
            float q2 = g_eml[1][j0 + row][tga];
            s1m[row][tt] = ok ? m1 : 0.f;
            s1e[row][tt] = ok ? e1 : 0.f;
            s1q[row][tt] = ok ? q1 : 0.f;
            s2m[row][tt] = ok ? m2 : 0.f;
            s2e[row][tt] = ok ? e2 : 0.f;
            s2q[row][tt] = ok ? q2 : 0.f;
        }
        __syncthreads();

        #pragma unroll
        for (int tt = 0; tt < 16; tt++) {
            float m1[4], e1[4], q1[4], m2[4], e2[4], q2[4];
            #pragma unroll
            for (int a = 0; a < 4; a++) {
                int r = ty + 16 * a;
                m1[a] = s1m[r][tt];
                e1[a] = s1e[r][tt];
                q1[a] = s1q[r][tt];
            }
            #pragma unroll
            for (int b = 0; b < 4; b++) {
                int r = tx + 16 * b;
                m2[b] = s2m[r][tt];
                e2[b] = s2e[r][tt];
                q2[b] = s2q[r][tt];
            }
            #pragma unroll
            for (int a = 0; a < 4; a++)
                #pragma unroll
                for (int b = 0; b < 4; b++) {
                    float d  = m1[a] - m2[b];
                    float dd = d * d;
                    acc[a][b] = fmaf(e1[a] + dd, q2[b], acc[a][b]);
                    acc[a][b] = fmaf(e2[b] + dd, q1[a], acc[a][b]);
                }
        }
    }

    #pragma unroll
    for (int a = 0; a < 4; a++) {
        int i = i0 + ty + 16 * a;
        #pragma unroll
        for (int b = 0; b < 4; b++) {
            int j = j0 + tx + 16 * b;
            g_spart[bz][i][j] = acc[a][b];
        }
    }
}

// ============================================================
// K4: assemble score + log_softmax + classes tail.
// ============================================================
__global__ void k_softmax(float* __restrict__ out, int out_size)
{
    const int i = blockIdx.x;
    const int j = threadIdx.x;
    __shared__ float red[256];

    float s = 0.f;
    #pragma unroll
    for (int z = 0; z < 8; z++) s += g_spart[z][i][j];

    float H0 = 0.5f * (float)T * LOG_2PIE;
    float H1 = H0;
    #pragma unroll
    for (int b = 0; b < 9; b++) {
        H0 += g_Hpart[b][i];
        H1 += g_Hpart[b][NEP + j];
    }
    float score = 0.5f * s - (float)T + H0 + H1;
    float v = -score;

    red[j] = v;
    __syncthreads();
    for (int st = 128; st > 0; st >>= 1) {
        if (j < st) red[j] = fmaxf(red[j], red[j + st]);
        __syncthreads();
    }
    float mx = red[0];
    __syncthreads();
    float ex = expf(v - mx);
    red[j] = ex;
    __syncthreads();
    for (int st = 128; st > 0; st >>= 1) {
        if (j < st) red[j] += red[j + st];
        __syncthreads();
    }
    float lse = mx + logf(red[0]);
    out[(size_t)i * NEP + j] = v - lse;

    if (j == 0 && NEP * NEP + i < out_size)
        out[NEP * NEP + i] = (float)i;
}

// ============================================================
extern "C" void kernel_launch(void* const* d_in, const int* in_sizes, int n_in,
                              void* d_out, int out_size)
{
    const float* train_inputs  = (const float*)d_in[0];
    const float* train_targets = (const float*)d_in[1];
    const float* test_inputs   = (const float*)d_in[2];
    const float* test_targets  = (const float*)d_in[3];
    const float* W_fe          = (const float*)d_in[4];
    const float* b_fe          = (const float*)d_in[5];
    const float* W_lv          = (const float*)d_in[6];
    const float* b_lv          = (const float*)d_in[7];
    float* out = (float*)d_out;

    const int smem_fgemm = 2 * FG_BUF;           // 141312
    const int smem_lv    = 2 * LV_BUF;           // 104448
    cudaFuncSetAttribute(k_fgemm,  cudaFuncAttributeMaxDynamicSharedMemorySize, smem_fgemm);
    cudaFuncSetAttribute(k_lvgemm, cudaFuncAttributeMaxDynamicSharedMemorySize, smem_lv);

    k_prep<<<19408, 256>>>(train_inputs, test_inputs, W_fe, W_lv,
                           train_targets, test_targets);
    k_fgemm<<<dim3(4, 64, 2), 256, smem_fgemm>>>(b_fe);
    k_split_z<<<1088, 256>>>();
    k_lvgemm<<<dim3(9, 8), 512, smem_lv>>>(b_lv);
    k_pairp<<<dim3(4, 4, 8), 256>>>();
    k_softmax<<<NEP, 256>>>(out, out_size);
}

// round 7
// speedup vs baseline: 4.1694x; 1.1014x over previous
#include <cuda_runtime.h>
#include <cuda_bf16.h>
#include <math.h>

#define NEP 256
#define NS  32
#define DIN 512
#define DF  512
#define T   1026
#define TT  513

#define LOG_2PIE 2.8378770664093453f

// K geometry for the logvar GEMM: K=1026 -> 513 k-pairs -> pad to 544 (17 chunks of 32)
#define LV_KP   544
#define LV_NPAD 1152   // 18 tiles of 64

// -------- device scratch (no allocations allowed) --------
__device__ float g_mu [2][NEP][T];   // z (mu)
__device__ float g_elv[2][NEP][T];   // exp(lv)
__device__ float g_eml[2][NEP][T];   // exp(-lv)
__device__ float g_Hpart[18][512];   // per-Ntile partial sums of lv per row (row = set*256+e)
__device__ float g_spart[8][NEP][NEP]; // pairwise score partials per t-slice

// bf16 split operands. Inputs: [set][8192 rows][256 k-pair words]
__device__ __align__(16) unsigned g_ihi[2][8192 * 256];
__device__ __align__(16) unsigned g_ilo[2][8192 * 256];
// W_fe split, k-pair interleaved
__device__ __align__(16) unsigned g_wphi[256 * 512];
__device__ __align__(16) unsigned g_wplo[256 * 512];
// z split: [512 rows (set*256+e)][544 k-pair words] == 1088 ushort halves per row.
// Halves t in [0,1026) written by k_fgemm epilogue / k_prep targets; pad [1026,1088)
// is never written and stays zero from module init.
__device__ __align__(16) unsigned g_zhi[512 * LV_KP];
__device__ __align__(16) unsigned g_zlo[512 * LV_KP];
// W_lv split (padded)
__device__ __align__(16) unsigned g_wlvh[LV_KP * LV_NPAD];
__device__ __align__(16) unsigned g_wlvl[LV_KP * LV_NPAD];

// ============================================================
__device__ __forceinline__ void split1(float x, unsigned short& h, unsigned short& l)
{
    __nv_bfloat16 bh = __float2bfloat16(x);
    float r = x - __bfloat162float(bh);
    __nv_bfloat16 bl = __float2bfloat16(r);
    h = __bfloat16_as_ushort(bh);
    l = __bfloat16_as_ushort(bl);
}

__device__ __forceinline__ void cp16(unsigned saddr, const void* g)
{
    asm volatile("cp.async.cg.shared.global [%0], [%1], 16;\n" :: "r"(saddr), "l"(g));
}
__device__ __forceinline__ unsigned s2u(const void* p)
{
    return (unsigned)__cvta_generic_to_shared(p);
}

// ============================================================
// merged prep: split inputs (16384) | W_fe (512) | W_lv (2448) | targets (64)
// grid = 19408 blocks x 256 threads
// ============================================================
__global__ void k_prep(const float* __restrict__ trin, const float* __restrict__ tein,
                       const float* __restrict__ Wfe, const float* __restrict__ Wlv,
                       const float* __restrict__ trtg, const float* __restrict__ tetg)
{
    const int b = blockIdx.x;
    const int tid = threadIdx.x;

    if (b < 16384) {
        // ---- split inputs ----
        const int set = b >> 13;
        const unsigned w = (unsigned)(b & 8191) * 256 + tid;   // 2,097,152 words per set
        const float2* src = (const float2*)(set ? tein : trin);
        float2 v = src[w];
        unsigned short h0, l0, h1, l1;
        split1(v.x, h0, l0);
        split1(v.y, h1, l1);
        g_ihi[set][w] = (unsigned)h0 | ((unsigned)h1 << 16);
        g_ilo[set][w] = (unsigned)l0 | ((unsigned)l1 << 16);
    } else if (b < 16896) {
        // ---- split W_fe ----
        const unsigned w = (b - 16384) * 256 + tid;            // 131072 words
        const int k2 = w >> 9;
        const int n  = w & 511;
        float x0 = Wfe[(size_t)(2 * k2) * DF + n];
        float x1 = Wfe[(size_t)(2 * k2 + 1) * DF + n];
        unsigned short h0, l0, h1, l1;
        split1(x0, h0, l0);
        split1(x1, h1, l1);
        g_wphi[w] = (unsigned)h0 | ((unsigned)h1 << 16);
        g_wplo[w] = (unsigned)l0 | ((unsigned)l1 << 16);
    } else if (b < 19344) {
        // ---- split W_lv (padded) ----
        const unsigned idx = (b - 16896) * 256 + tid;          // up to 626688
        if (idx >= (unsigned)LV_KP * LV_NPAD) return;
        const int k2 = idx / LV_NPAD;
        const int n  = idx % LV_NPAD;
        const int k = 2 * k2;
        float x0 = (k     < T && n < T) ? Wlv[(size_t)k * T + n]       : 0.f;
        float x1 = (k + 1 < T && n < T) ? Wlv[(size_t)(k + 1) * T + n] : 0.f;
        unsigned short h0, l0, h1, l1;
        split1(x0, h0, l0);
        split1(x1, h1, l1);
        g_wlvh[idx] = (unsigned)h0 | ((unsigned)h1 << 16);
        g_wlvl[idx] = (unsigned)l0 | ((unsigned)l1 << 16);
    } else {
        // ---- targets: one warp per (set, episode) ----
        const int w = (b - 19344) * 8 + (tid >> 5);            // 0..511
        const int lane = tid & 31;
        const int set = w >> 8, e = w & 255;
        const float* tg = (set ? tetg : trtg) + (size_t)e * NS;
        float x = tg[lane];
        float s = x;
        #pragma unroll
        for (int off = 16; off > 0; off >>= 1) s += __shfl_xor_sync(0xffffffffu, s, off);
        float m = s * (1.f / NS);
        float d = x - m;
        float q = d * d;
        #pragma unroll
        for (int off = 16; off > 0; off >>= 1) q += __shfl_xor_sync(0xffffffffu, q, off);
        if (lane == 0) {
            float sd = sqrtf(q * (1.f / (NS - 1)));
            g_mu[set][e][0]  = m;
            g_mu[set][e][TT] = sd;
            // z-split halves for t=0 and t=TT
            unsigned short* zh = (unsigned short*)g_zhi;
            unsigned short* zl = (unsigned short*)g_zlo;
            const unsigned base = (unsigned)(set * 256 + e) * (2 * LV_KP);
            unsigned short h0, l0, h1, l1;
            split1(m,  h0, l0);
            split1(sd, h1, l1);
            zh[base + 0]  = h0;  zl[base + 0]  = l0;
            zh[base + TT] = h1;  zl[base + TT] = l1;
        }
    }
}

// ============================================================
// mma helper
// ============================================================
__device__ __forceinline__ void mma16816(float* d, const unsigned* a, const unsigned* b)
{
    asm volatile(
        "mma.sync.aligned.m16n8k16.row.col.f32.bf16.bf16.f32 "
        "{%0,%1,%2,%3}, {%4,%5,%6,%7}, {%8,%9}, {%0,%1,%2,%3};\n"
        : "+f"(d[0]), "+f"(d[1]), "+f"(d[2]), "+f"(d[3])
        : "r"(a[0]), "r"(a[1]), "r"(a[2]), "r"(a[3]), "r"(b[0]), "r"(b[1]));
}

#define AS_STRIDE 36   // uint32 words per A row (72 halves)
#define BS_STRIDE 132  // uint32 words per 128-wide B k2-row / floats per C row

// ============================================================
// K1: tensor-core feature GEMM, cp.async double-buffered.
// Block 128x128, 256 threads (8 warps, 2x4 grid of 64x32 warp tiles).
// Fused bias/relu/mean/std epilogue + direct z-split store. grid (4,64,2).
// ============================================================
#define FG_BUF 70656

__global__ __launch_bounds__(256, 1)
void k_fgemm(const float* __restrict__ bfe)
{
    extern __shared__ unsigned char smem[];
    const int ct  = blockIdx.x;
    const int eg  = blockIdx.y;
    const int set = blockIdx.z;
    const int tid = threadIdx.x;
    const int wid = tid >> 5;
    const int lid = tid & 31;
    const int wm  = wid >> 2;        // 0..1 : 64-row warp tile
    const int wn  = wid & 3;         // 0..3 : 32-col warp tile
    const int gid = lid >> 2;
    const int tig = lid & 3;

    const unsigned* gih = g_ihi[set];
    const unsigned* gil = g_ilo[set];

    float acc[4][4][4];
    #pragma unroll
    for (int mt = 0; mt < 4; mt++)
        #pragma unroll
        for (int nt = 0; nt < 4; nt++)
            #pragma unroll
            for (int r = 0; r < 4; r++) acc[mt][nt][r] = 0.f;

    auto stage = [&](int c, int buf) {
        unsigned* Aw0 = (unsigned*)(smem + buf * FG_BUF);
        unsigned* Aw1 = (unsigned*)(smem + buf * FG_BUF + 18432);
        unsigned* Bw0 = (unsigned*)(smem + buf * FG_BUF + 36864);
        unsigned* Bw1 = (unsigned*)(smem + buf * FG_BUF + 53760);
        #pragma unroll
        for (int i = 0; i < 4; i++) {
            int u = tid + i * 256;                 // 1024 16B units per term
            int row = u >> 3, kp = (u & 7) * 4;
            unsigned srci = (unsigned)(eg * 128 + row) * 256 + c * 32 + kp;
            cp16(s2u(&Aw0[row * AS_STRIDE + kp]), &gih[srci]);
            cp16(s2u(&Aw1[row * AS_STRIDE + kp]), &gil[srci]);
        }
        #pragma unroll
        for (int i = 0; i < 4; i++) {
            int u = tid + i * 256;
            int k2 = u >> 5, nl = (u & 31) * 4;
            unsigned srci = (unsigned)(c * 32 + k2) * 512 + ct * 128 + nl;
            cp16(s2u(&Bw0[k2 * BS_STRIDE + nl]), &g_wphi[srci]);
            cp16(s2u(&Bw1[k2 * BS_STRIDE + nl]), &g_wplo[srci]);
        }
        asm volatile("cp.async.commit_group;\n" ::: "memory");
    };

    stage(0, 0);

    for (int chunk = 0; chunk < 8; chunk++) {
        if (chunk < 7) {
            stage(chunk + 1, (chunk + 1) & 1);
            asm volatile("cp.async.wait_group 1;\n" ::: "memory");
        } else {
            asm volatile("cp.async.wait_group 0;\n" ::: "memory");
        }
        __syncthreads();

        const int buf = chunk & 1;
        unsigned* Aw0 = (unsigned*)(smem + buf * FG_BUF);
        unsigned* Aw1 = (unsigned*)(smem + buf * FG_BUF + 18432);
        unsigned* Bw0 = (unsigned*)(smem + buf * FG_BUF + 36864);
        unsigned* Bw1 = (unsigned*)(smem + buf * FG_BUF + 53760);

        #pragma unroll
        for (int ks = 0; ks < 4; ks++) {
            const int cw = ks * 8 + tig;
            unsigned b[4][2][2];
            #pragma unroll
            for (int nt = 0; nt < 4; nt++) {
                int n = wn * 32 + nt * 8 + gid;
                b[nt][0][0] = Bw0[cw * BS_STRIDE + n];
                b[nt][0][1] = Bw0[(cw + 4) * BS_STRIDE + n];
                b[nt][1][0] = Bw1[cw * BS_STRIDE + n];
                b[nt][1][1] = Bw1[(cw + 4) * BS_STRIDE + n];
            }
            #pragma unroll
            for (int mt = 0; mt < 4; mt++) {
                unsigned a[2][4];
                int r0 = wm * 64 + mt * 16 + gid;
                a[0][0] = Aw0[r0 * AS_STRIDE + cw];
                a[0][1] = Aw0[(r0 + 8) * AS_STRIDE + cw];
                a[0][2] = Aw0[r0 * AS_STRIDE + cw + 4];
                a[0][3] = Aw0[(r0 + 8) * AS_STRIDE + cw + 4];
                a[1][0] = Aw1[r0 * AS_STRIDE + cw];
                a[1][1] = Aw1[(r0 + 8) * AS_STRIDE + cw];
                a[1][2] = Aw1[r0 * AS_STRIDE + cw + 4];
                a[1][3] = Aw1[(r0 + 8) * AS_STRIDE + cw + 4];
                #pragma unroll
                for (int nt = 0; nt < 4; nt++) {
                    mma16816(acc[mt][nt], a[0], b[nt][0]);
                    mma16816(acc[mt][nt], a[0], b[nt][1]);
                    mma16816(acc[mt][nt], a[1], b[nt][0]);
                }
            }
        }
        __syncthreads();
    }

    float* Cs = (float*)smem;     // [128][132]
    #pragma unroll
    for (int mt = 0; mt < 4; mt++) {
        int r0 = wm * 64 + mt * 16 + gid;
        #pragma unroll
        for (int nt = 0; nt < 4; nt++) {
            int c = wn * 32 + nt * 8 + tig * 2;
            *(float2*)&Cs[r0 * BS_STRIDE + c]       = make_float2(acc[mt][nt][0], acc[mt][nt][1]);
            *(float2*)&Cs[(r0 + 8) * BS_STRIDE + c] = make_float2(acc[mt][nt][2], acc[mt][nt][3]);
        }
    }
    __syncthreads();

    {
        const int j  = tid & 127;
        const int f  = ct * 128 + j;
        const float bias = bfe[f];
        unsigned short* zh = (unsigned short*)g_zhi;
        unsigned short* zl = (unsigned short*)g_zlo;
        #pragma unroll
        for (int half = 0; half < 2; half++) {
            const int ep = (tid >> 7) * 2 + half;   // 0..3
            float s = 0.f, ss = 0.f;
            #pragma unroll
            for (int m = 0; m < NS; m++) {
                float v = Cs[(ep * 32 + m) * BS_STRIDE + j] + bias;
                v = fmaxf(v, 0.f);
                s += v;
                ss = fmaf(v, v, ss);
            }
            float mean = s * (1.f / NS);
            float var  = (ss - s * mean) * (1.f / (NS - 1));
            float stdv = sqrtf(fmaxf(var, 0.f));
            int e = eg * 4 + ep;
            g_mu[set][e][1 + f]      = mean;
            g_mu[set][e][TT + 1 + f] = stdv;
            // direct z-split (replaces k_split_z)
            const unsigned base = (unsigned)(set * 256 + e) * (2 * LV_KP);
            unsigned short h0, l0, h1, l1;
            split1(mean, h0, l0);
            split1(stdv, h1, l1);
            zh[base + 1 + f]      = h0;  zl[base + 1 + f]      = l0;
            zh[base + TT + 1 + f] = h1;  zl[base + TT + 1 + f] = l1;
        }
    }
}

// ============================================================
// K2: logvar GEMM on tensor cores, cp.async double-buffered.
// Block 64x64, grid (18,8) = 144 blocks, 256 threads
// (8 warps as 2x4; warp tile 32x16, 2x2 acc tiles).
// Epilogue: +b_lv, clip, exp(+-lv), partial H into g_Hpart.
// ============================================================
#define LVB_STRIDE 68
#define LV_BUF 35840   // A: 2*9216, B: 2*8704

__global__ __launch_bounds__(256, 1)
void k_lvgemm(const float* __restrict__ blv)
{
    extern __shared__ unsigned char smem[];

    const int bn  = blockIdx.x;      // N tile (64 cols)
    const int bm  = blockIdx.y;      // M tile (64 rows)
    const int tid = threadIdx.x;
    const int wid = tid >> 5;
    const int lid = tid & 31;
    const int wm  = wid >> 2;        // 0..1 : 32-row warp tile
    const int wn  = wid & 3;         // 0..3 : 16-col warp tile
    const int gid = lid >> 2;
    const int tig = lid & 3;

    float acc[2][2][4];
    #pragma unroll
    for (int mt = 0; mt < 2; mt++)
        #pragma unroll
        for (int nt = 0; nt < 2; nt++)
            #pragma unroll
            for (int r = 0; r < 4; r++) acc[mt][nt][r] = 0.f;

    auto stage = [&](int c, int buf) {
        unsigned* Aw0 = (unsigned*)(smem + buf * LV_BUF);
        unsigned* Aw1 = (unsigned*)(smem + buf * LV_BUF + 9216);
        unsigned* Bw0 = (unsigned*)(smem + buf * LV_BUF + 18432);
        unsigned* Bw1 = (unsigned*)(smem + buf * LV_BUF + 27136);
        #pragma unroll
        for (int i = 0; i < 2; i++) {
            int u = tid + i * 256;                  // 512 16B units per term
            int row = u >> 3, kp = (u & 7) * 4;
            unsigned srci = (unsigned)(bm * 64 + row) * LV_KP + c * 32 + kp;
            cp16(s2u(&Aw0[row * AS_STRIDE + kp]), &g_zhi[srci]);
            cp16(s2u(&Aw1[row * AS_STRIDE + kp]), &g_zlo[srci]);
        }
        #pragma unroll
        for (int i = 0; i < 2; i++) {
            int u = tid + i * 256;                  // 512 units per term
            int k2 = u >> 4, nl = (u & 15) * 4;
            unsigned srci = (unsigned)(c * 32 + k2) * LV_NPAD + bn * 64 + nl;
            cp16(s2u(&Bw0[k2 * LVB_STRIDE + nl]), &g_wlvh[srci]);
            cp16(s2u(&Bw1[k2 * LVB_STRIDE + nl]), &g_wlvl[srci]);
        }
        asm volatile("cp.async.commit_group;\n" ::: "memory");
    };

    stage(0, 0);

    for (int chunk = 0; chunk < 17; chunk++) {
        if (chunk < 16) {
            stage(chunk + 1, (chunk + 1) & 1);
            asm volatile("cp.async.wait_group 1;\n" ::: "memory");
        } else {
            asm volatile("cp.async.wait_group 0;\n" ::: "memory");
        }
        __syncthreads();

        const int buf = chunk & 1;
        unsigned* Aw0 = (unsigned*)(smem + buf * LV_BUF);
        unsigned* Aw1 = (unsigned*)(smem + buf * LV_BUF + 9216);
        unsigned* Bw0 = (unsigned*)(smem + buf * LV_BUF + 18432);
        unsigned* Bw1 = (unsigned*)(smem + buf * LV_BUF + 27136);

        #pragma unroll
        for (int ks = 0; ks < 4; ks++) {
            const int cw = ks * 8 + tig;
            unsigned b[2][2][2];
            #pragma unroll
            for (int nt = 0; nt < 2; nt++) {
                int n = wn * 16 + nt * 8 + gid;
                b[nt][0][0] = Bw0[cw * LVB_STRIDE + n];
                b[nt][0][1] = Bw0[(cw + 4) * LVB_STRIDE + n];
                b[nt][1][0] = Bw1[cw * LVB_STRIDE + n];
                b[nt][1][1] = Bw1[(cw + 4) * LVB_STRIDE + n];
            }
            #pragma unroll
            for (int mt = 0; mt < 2; mt++) {
                unsigned a[2][4];
                int r0 = wm * 32 + mt * 16 + gid;
                a[0][0] = Aw0[r0 * AS_STRIDE + cw];
                a[0][1] = Aw0[(r0 + 8) * AS_STRIDE + cw];
                a[0][2] = Aw0[r0 * AS_STRIDE + cw + 4];
                a[0][3] = Aw0[(r0 + 8) * AS_STRIDE + cw + 4];
                a[1][0] = Aw1[r0 * AS_STRIDE + cw];
                a[1][1] = Aw1[(r0 + 8) * AS_STRIDE + cw];
                a[1][2] = Aw1[r0 * AS_STRIDE + cw + 4];
                a[1][3] = Aw1[(r0 + 8) * AS_STRIDE + cw + 4];
                #pragma unroll
                for (int nt = 0; nt < 2; nt++) {
                    mma16816(acc[mt][nt], a[0], b[nt][0]);
                    mma16816(acc[mt][nt], a[0], b[nt][1]);
                    mma16816(acc[mt][nt], a[1], b[nt][0]);
                }
            }
        }
        __syncthreads();
    }

    float* Cs = (float*)smem;                  // [64][68]
    float* hq = (float*)(smem + 17408);        // [64][2]
    #pragma unroll
    for (int mt = 0; mt < 2; mt++) {
        int r0 = wm * 32 + mt * 16 + gid;
        #pragma unroll
        for (int nt = 0; nt < 2; nt++) {
            int c = wn * 16 + nt * 8 + tig * 2;
            *(float2*)&Cs[r0 * LVB_STRIDE + c]       = make_float2(acc[mt][nt][0], acc[mt][nt][1]);
            *(float2*)&Cs[(r0 + 8) * LVB_STRIDE + c] = make_float2(acc[mt][nt][2], acc[mt][nt][3]);
        }
    }
    __syncthreads();

    {
        const int j    = tid & 63;          // column within tile
        const int rg   = tid >> 6;          // 0..3 : 16-row group
        const int w2   = (tid >> 5) & 1;    // which warp-half of the 64 cols
        const int lane = tid & 31;
        const int n = bn * 64 + j;
        const bool valid = (n < T);
        const float bias = valid ? blv[n] : 0.f;

        #pragma unroll
        for (int rr = 0; rr < 16; rr++) {
            int r = rg * 16 + rr;
            float lv = fminf(fmaxf(Cs[r * LVB_STRIDE + j] + bias, -9.f), -2.f);
            float h = valid ? lv : 0.f;
            if (valid) {
                int grow = bm * 64 + r;
                int set = grow >> 8, e = grow & 255;
                g_elv[set][e][n] = expf(lv);
                g_eml[set][e][n] = expf(-lv);
            }
            #pragma unroll
            for (int off = 16; off > 0; off >>= 1)
                h += __shfl_down_sync(0xffffffffu, h, off);
            if (lane == 0) hq[r * 2 + w2] = h;
        }
    }
    __syncthreads();
    if (tid < 64) {
        g_Hpart[bn][bm * 64 + tid] = hq[tid * 2] + hq[tid * 2 + 1];
    }
}

// ============================================================
// K3: pairwise score partials, register-tiled 4x4, t-sliced.
// ============================================================
__global__ __launch_bounds__(256)
void k_pairp()
{
    __shared__ float s1m[64][17], s1e[64][17], s1q[64][17];
    __shared__ float s2m[64][17], s2e[64][17], s2q[64][17];
    const int tid = threadIdx.x;
    const int ty = tid >> 4, tx = tid & 15;
    const int i0 = blockIdx.y * 64;
    const int j0 = blockIdx.x * 64;
    const int bz = blockIdx.z;
    const int t_beg = bz * 129;
    const int t_end = min(T, t_beg + 129);

    float acc[4][4];
    #pragma unroll
    for (int a = 0; a < 4; a++)
        #pragma unroll
        for (int b = 0; b < 4; b++) acc[a][b] = 0.f;

    for (int c0 = t_beg; c0 < t_end; c0 += 16) {
        __syncthreads();
        #pragma unroll
        for (int u4 = 0; u4 < 4; u4++) {
            int u = tid + u4 * 256;
            int row = u >> 4, tt = u & 15;
            int tg = c0 + tt;
            bool ok = tg < t_end;
            int tga = ok ? tg : 0;
            float m1 = g_mu [0][i0 + row][tga];
            float e1 = g_elv[0][i0 + row][tga];
            float q1 = g_eml[0][i0 + row][tga];
            float m2 = g_mu [1][j0 + row][tga];
            float e2 = g_elv[1][j0 + row][tga];
            float q2 = g_eml[1][j0 + row][tga];
            s1m[row][tt] = ok ? m1 : 0.f;
            s1e[row][tt] = ok ? e1 : 0.f;
            s1q[row][tt] = ok ? q1 : 0.f;
            s2m[row][tt] = ok ? m2 : 0.f;
            s2e[row][tt] = ok ? e2 : 0.f;
            s2q[row][tt] = ok ? q2 : 0.f;
        }
        __syncthreads();

        #pragma unroll
        for (int tt = 0; tt < 16; tt++) {
            float m1[4], e1[4], q1[4], m2[4], e2[4], q2[4];
            #pragma unroll
            for (int a = 0; a < 4; a++) {
                int r = ty + 16 * a;
                m1[a] = s1m[r][tt];
                e1[a] = s1e[r][tt];
                q1[a] = s1q[r][tt];
            }
            #pragma unroll
            for (int b = 0; b < 4; b++) {
                int r = tx + 16 * b;
                m2[b] = s2m[r][tt];
                e2[b] = s2e[r][tt];
                q2[b] = s2q[r][tt];
            }
            #pragma unroll
            for (int a = 0; a < 4; a++)
                #pragma unroll
                for (int b = 0; b < 4; b++) {
                    float d  = m1[a] - m2[b];
                    float dd = d * d;
                    acc[a][b] = fmaf(e1[a] + dd, q2[b], acc[a][b]);
                    acc[a][b] = fmaf(e2[b] + dd, q1[a], acc[a][b]);
                }
        }
    }

    #pragma unroll
    for (int a = 0; a < 4; a++) {
        int i = i0 + ty + 16 * a;
        #pragma unroll
        for (int b = 0; b < 4; b++) {
            int j = j0 + tx + 16 * b;
            g_spart[bz][i][j] = acc[a][b];
        }
    }
}

// ============================================================
// K4: assemble score + log_softmax + classes tail.
// ============================================================
__global__ void k_softmax(float* __restrict__ out, int out_size)
{
    const int i = blockIdx.x;
    const int j = threadIdx.x;
    __shared__ float red[256];

    float s = 0.f;
    #pragma unroll
    for (int z = 0; z < 8; z++) s += g_spart[z][i][j];

    float H0 = 0.5f * (float)T * LOG_2PIE;
    float H1 = H0;
    #pragma unroll
    for (int b = 0; b < 18; b++) {
        H0 += g_Hpart[b][i];
        H1 += g_Hpart[b][NEP + j];
    }
    float score = 0.5f * s - (float)T + H0 + H1;
    float v = -score;

    red[j] = v;
    __syncthreads();
    for (int st = 128; st > 0; st >>= 1) {
        if (j < st) red[j] = fmaxf(red[j], red[j + st]);
        __syncthreads();
    }
    float mx = red[0];
    __syncthreads();
    float ex = expf(v - mx);
    red[j] = ex;
    __syncthreads();
    for (int st = 128; st > 0; st >>= 1) {
        if (j < st) red[j] += red[j + st];
        __syncthreads();
    }
    float lse = mx + logf(red[0]);
    out[(size_t)i * NEP + j] = v - lse;

    if (j == 0 && NEP * NEP + i < out_size)
        out[NEP * NEP + i] = (float)i;
}

// ============================================================
extern "C" void kernel_launch(void* const* d_in, const int* in_sizes, int n_in,
                              void* d_out, int out_size)
{
    const float* train_inputs  = (const float*)d_in[0];
    const float* train_targets = (const float*)d_in[1];
    const float* test_inputs   = (const float*)d_in[2];
    const float* test_targets  = (const float*)d_in[3];
    const float* W_fe          = (const float*)d_in[4];
    const float* b_fe          = (const float*)d_in[5];
    const float* W_lv          = (const float*)d_in[6];
    const float* b_lv          = (const float*)d_in[7];
    float* out = (float*)d_out;

    const int smem_fgemm = 2 * FG_BUF;           // 141312
    const int smem_lv    = 2 * LV_BUF;           // 71680
    cudaFuncSetAttribute(k_fgemm,  cudaFuncAttributeMaxDynamicSharedMemorySize, smem_fgemm);
    cudaFuncSetAttribute(k_lvgemm, cudaFuncAttributeMaxDynamicSharedMemorySize, smem_lv);

    k_prep<<<19408, 256>>>(train_inputs, test_inputs, W_fe, W_lv,
                           train_targets, test_targets);
    k_fgemm<<<dim3(4, 64, 2), 256, smem_fgemm>>>(b_fe);
    k_lvgemm<<<dim3(18, 8), 256, smem_lv>>>(b_lv);
    k_pairp<<<dim3(4, 4, 8), 256>>>();
    k_softmax<<<NEP, 256>>>(out, out_size);
}

// round 8
// speedup vs baseline: 4.6366x; 1.1121x over previous
#include <cuda_runtime.h>
#include <cuda_bf16.h>
#include <math.h>

#define NEP 256
#define NS  32
#define DIN 512
#define DF  512
#define T   1026
#define TT  513

#define LOG_2PIE 2.8378770664093453f

// K geometry for the logvar GEMM: K=1026 -> 513 k-pairs -> pad to 544 (17 chunks of 32)
#define LV_KP   544
#define LV_NPAD 1152   // 18 tiles of 64

// pair-GEMM K geometry: K = 4*1026 = 4104 -> 2052 pairs -> pad to 2080 (65 chunks of 32)
#define PK_STRIDE 2080
#define PK_CHUNKS 65

// -------- device scratch (no allocations allowed) --------
__device__ float g_mu [2][NEP][T];   // z (mu)
__device__ float g_Hpart[18][512];   // per-Ntile partial sums of lv per row (row = set*256+e)
__device__ float g_Mpart[18][512];   // per-Ntile partial sums of m^2*exp(-lv) per row
__device__ float g_spart[8][NEP][NEP]; // pairwise score partials per K-slice

// bf16 split operands. Inputs: [set][8192 rows][256 k-pair words]
__device__ __align__(16) unsigned g_ihi[2][8192 * 256];
__device__ __align__(16) unsigned g_ilo[2][8192 * 256];
// W_fe split, k-pair interleaved
__device__ __align__(16) unsigned g_wphi[256 * 512];
__device__ __align__(16) unsigned g_wplo[256 * 512];
// z split: [512 rows (set*256+e)][544 k-pair words]; pad never written (zero-init)
__device__ __align__(16) unsigned g_zhi[512 * LV_KP];
__device__ __align__(16) unsigned g_zlo[512 * LV_KP];
// W_lv split (padded)
__device__ __align__(16) unsigned g_wlvh[LV_KP * LV_NPAD];
__device__ __align__(16) unsigned g_wlvl[LV_KP * LV_NPAD];
// pairwise feature rows, bf16 split, k = 4*n + f (f=0..3), pad zero-init
// A (set 0): [e+m^2, q, m*q, m];  B (set 1): [q, e+m^2, -2m, -2m*q]   (q = exp(-lv), e = exp(lv))
__device__ __align__(16) unsigned g_pAhi[NEP * PK_STRIDE];
__device__ __align__(16) unsigned g_pAlo[NEP * PK_STRIDE];
__device__ __align__(16) unsigned g_pBhi[NEP * PK_STRIDE];
__device__ __align__(16) unsigned g_pBlo[NEP * PK_STRIDE];

// ============================================================
__device__ __forceinline__ void split1(float x, unsigned short& h, unsigned short& l)
{
    __nv_bfloat16 bh = __float2bfloat16(x);
    float r = x - __bfloat162float(bh);
    __nv_bfloat16 bl = __float2bfloat16(r);
    h = __bfloat16_as_ushort(bh);
    l = __bfloat16_as_ushort(bl);
}

__device__ __forceinline__ void cp16(unsigned saddr, const void* g)
{
    asm volatile("cp.async.cg.shared.global [%0], [%1], 16;\n" :: "r"(saddr), "l"(g));
}
__device__ __forceinline__ unsigned s2u(const void* p)
{
    return (unsigned)__cvta_generic_to_shared(p);
}

// ============================================================
// merged prep: split inputs (16384) | W_fe (512) | W_lv (2448) | targets (64)
// ============================================================
__global__ void k_prep(const float* __restrict__ trin, const float* __restrict__ tein,
                       const float* __restrict__ Wfe, const float* __restrict__ Wlv,
                       const float* __restrict__ trtg, const float* __restrict__ tetg)
{
    const int b = blockIdx.x;
    const int tid = threadIdx.x;

    if (b < 16384) {
        const int set = b >> 13;
        const unsigned w = (unsigned)(b & 8191) * 256 + tid;
        const float2* src = (const float2*)(set ? tein : trin);
        float2 v = src[w];
        unsigned short h0, l0, h1, l1;
        split1(v.x, h0, l0);
        split1(v.y, h1, l1);
        g_ihi[set][w] = (unsigned)h0 | ((unsigned)h1 << 16);
        g_ilo[set][w] = (unsigned)l0 | ((unsigned)l1 << 16);
    } else if (b < 16896) {
        const unsigned w = (b - 16384) * 256 + tid;
        const int k2 = w >> 9;
        const int n  = w & 511;
        float x0 = Wfe[(size_t)(2 * k2) * DF + n];
        float x1 = Wfe[(size_t)(2 * k2 + 1) * DF + n];
        unsigned short h0, l0, h1, l1;
        split1(x0, h0, l0);
        split1(x1, h1, l1);
        g_wphi[w] = (unsigned)h0 | ((unsigned)h1 << 16);
        g_wplo[w] = (unsigned)l0 | ((unsigned)l1 << 16);
    } else if (b < 19344) {
        const unsigned idx = (b - 16896) * 256 + tid;
        if (idx >= (unsigned)LV_KP * LV_NPAD) return;
        const int k2 = idx / LV_NPAD;
        const int n  = idx % LV_NPAD;
        const int k = 2 * k2;
        float x0 = (k     < T && n < T) ? Wlv[(size_t)k * T + n]       : 0.f;
        float x1 = (k + 1 < T && n < T) ? Wlv[(size_t)(k + 1) * T + n] : 0.f;
        unsigned short h0, l0, h1, l1;
        split1(x0, h0, l0);
        split1(x1, h1, l1);
        g_wlvh[idx] = (unsigned)h0 | ((unsigned)h1 << 16);
        g_wlvl[idx] = (unsigned)l0 | ((unsigned)l1 << 16);
    } else {
        const int w = (b - 19344) * 8 + (tid >> 5);
        const int lane = tid & 31;
        const int set = w >> 8, e = w & 255;
        const float* tg = (set ? tetg : trtg) + (size_t)e * NS;
        float x = tg[lane];
        float s = x;
        #pragma unroll
        for (int off = 16; off > 0; off >>= 1) s += __shfl_xor_sync(0xffffffffu, s, off);
        float m = s * (1.f / NS);
        float d = x - m;
        float q = d * d;
        #pragma unroll
        for (int off = 16; off > 0; off >>= 1) q += __shfl_xor_sync(0xffffffffu, q, off);
        if (lane == 0) {
            float sd = sqrtf(q * (1.f / (NS - 1)));
            g_mu[set][e][0]  = m;
            g_mu[set][e][TT] = sd;
            unsigned short* zh = (unsigned short*)g_zhi;
            unsigned short* zl = (unsigned short*)g_zlo;
            const unsigned base = (unsigned)(set * 256 + e) * (2 * LV_KP);
            unsigned short h0, l0, h1, l1;
            split1(m,  h0, l0);
            split1(sd, h1, l1);
            zh[base + 0]  = h0;  zl[base + 0]  = l0;
            zh[base + TT] = h1;  zl[base + TT] = l1;
        }
    }
}

// ============================================================
// mma helper
// ============================================================
__device__ __forceinline__ void mma16816(float* d, const unsigned* a, const unsigned* b)
{
    asm volatile(
        "mma.sync.aligned.m16n8k16.row.col.f32.bf16.bf16.f32 "
        "{%0,%1,%2,%3}, {%4,%5,%6,%7}, {%8,%9}, {%0,%1,%2,%3};\n"
        : "+f"(d[0]), "+f"(d[1]), "+f"(d[2]), "+f"(d[3])
        : "r"(a[0]), "r"(a[1]), "r"(a[2]), "r"(a[3]), "r"(b[0]), "r"(b[1]));
}

#define AS_STRIDE 36   // uint32 words per 32-word-wide smem row (+4 pad)
#define BS_STRIDE 132  // uint32 words per 128-wide B k2-row / floats per C row

// ============================================================
// K1: tensor-core feature GEMM, cp.async double-buffered.
// Block 128x128, 256 threads. Fused bias/relu/mean/std + z-split. grid (4,64,2).
// ============================================================
#define FG_BUF 70656

__global__ __launch_bounds__(256, 1)
void k_fgemm(const float* __restrict__ bfe)
{
    extern __shared__ unsigned char smem[];
    const int ct  = blockIdx.x;
    const int eg  = blockIdx.y;
    const int set = blockIdx.z;
    const int tid = threadIdx.x;
    const int wid = tid >> 5;
    const int lid = tid & 31;
    const int wm  = wid >> 2;
    const int wn  = wid & 3;
    const int gid = lid >> 2;
    const int tig = lid & 3;

    const unsigned* gih = g_ihi[set];
    const unsigned* gil = g_ilo[set];

    float acc[4][4][4];
    #pragma unroll
    for (int mt = 0; mt < 4; mt++)
        #pragma unroll
        for (int nt = 0; nt < 4; nt++)
            #pragma unroll
            for (int r = 0; r < 4; r++) acc[mt][nt][r] = 0.f;

    auto stage = [&](int c, int buf) {
        unsigned* Aw0 = (unsigned*)(smem + buf * FG_BUF);
        unsigned* Aw1 = (unsigned*)(smem + buf * FG_BUF + 18432);
        unsigned* Bw0 = (unsigned*)(smem + buf * FG_BUF + 36864);
        unsigned* Bw1 = (unsigned*)(smem + buf * FG_BUF + 53760);
        #pragma unroll
        for (int i = 0; i < 4; i++) {
            int u = tid + i * 256;
            int row = u >> 3, kp = (u & 7) * 4;
            unsigned srci = (unsigned)(eg * 128 + row) * 256 + c * 32 + kp;
            cp16(s2u(&Aw0[row * AS_STRIDE + kp]), &gih[srci]);
            cp16(s2u(&Aw1[row * AS_STRIDE + kp]), &gil[srci]);
        }
        #pragma unroll
        for (int i = 0; i < 4; i++) {
            int u = tid + i * 256;
            int k2 = u >> 5, nl = (u & 31) * 4;
            unsigned srci = (unsigned)(c * 32 + k2) * 512 + ct * 128 + nl;
            cp16(s2u(&Bw0[k2 * BS_STRIDE + nl]), &g_wphi[srci]);
            cp16(s2u(&Bw1[k2 * BS_STRIDE + nl]), &g_wplo[srci]);
        }
        asm volatile("cp.async.commit_group;\n" ::: "memory");
    };

    stage(0, 0);

    for (int chunk = 0; chunk < 8; chunk++) {
        if (chunk < 7) {
            stage(chunk + 1, (chunk + 1) & 1);
            asm volatile("cp.async.wait_group 1;\n" ::: "memory");
        } else {
            asm volatile("cp.async.wait_group 0;\n" ::: "memory");
        }
        __syncthreads();

        const int buf = chunk & 1;
        unsigned* Aw0 = (unsigned*)(smem + buf * FG_BUF);
        unsigned* Aw1 = (unsigned*)(smem + buf * FG_BUF + 18432);
        unsigned* Bw0 = (unsigned*)(smem + buf * FG_BUF + 36864);
        unsigned* Bw1 = (unsigned*)(smem + buf * FG_BUF + 53760);

        #pragma unroll
        for (int ks = 0; ks < 4; ks++) {
            const int cw = ks * 8 + tig;
            unsigned b[4][2][2];
            #pragma unroll
            for (int nt = 0; nt < 4; nt++) {
                int n = wn * 32 + nt * 8 + gid;
                b[nt][0][0] = Bw0[cw * BS_STRIDE + n];
                b[nt][0][1] = Bw0[(cw + 4) * BS_STRIDE + n];
                b[nt][1][0] = Bw1[cw * BS_STRIDE + n];
                b[nt][1][1] = Bw1[(cw + 4) * BS_STRIDE + n];
            }
            #pragma unroll
            for (int mt = 0; mt < 4; mt++) {
                unsigned a[2][4];
                int r0 = wm * 64 + mt * 16 + gid;
                a[0][0] = Aw0[r0 * AS_STRIDE + cw];
                a[0][1] = Aw0[(r0 + 8) * AS_STRIDE + cw];
                a[0][2] = Aw0[r0 * AS_STRIDE + cw + 4];
                a[0][3] = Aw0[(r0 + 8) * AS_STRIDE + cw + 4];
                a[1][0] = Aw1[r0 * AS_STRIDE + cw];
                a[1][1] = Aw1[(r0 + 8) * AS_STRIDE + cw];
                a[1][2] = Aw1[r0 * AS_STRIDE + cw + 4];
                a[1][3] = Aw1[(r0 + 8) * AS_STRIDE + cw + 4];
                #pragma unroll
                for (int nt = 0; nt < 4; nt++) {
                    mma16816(acc[mt][nt], a[0], b[nt][0]);
                    mma16816(acc[mt][nt], a[0], b[nt][1]);
                    mma16816(acc[mt][nt], a[1], b[nt][0]);
                }
            }
        }
        __syncthreads();
    }

    float* Cs = (float*)smem;     // [128][132]
    #pragma unroll
    for (int mt = 0; mt < 4; mt++) {
        int r0 = wm * 64 + mt * 16 + gid;
        #pragma unroll
        for (int nt = 0; nt < 4; nt++) {
            int c = wn * 32 + nt * 8 + tig * 2;
            *(float2*)&Cs[r0 * BS_STRIDE + c]       = make_float2(acc[mt][nt][0], acc[mt][nt][1]);
            *(float2*)&Cs[(r0 + 8) * BS_STRIDE + c] = make_float2(acc[mt][nt][2], acc[mt][nt][3]);
        }
    }
    __syncthreads();

    {
        const int j  = tid & 127;
        const int f  = ct * 128 + j;
        const float bias = bfe[f];
        unsigned short* zh = (unsigned short*)g_zhi;
        unsigned short* zl = (unsigned short*)g_zlo;
        #pragma unroll
        for (int half = 0; half < 2; half++) {
            const int ep = (tid >> 7) * 2 + half;   // 0..3
            float s = 0.f, ss = 0.f;
            #pragma unroll
            for (int m = 0; m < NS; m++) {
                float v = Cs[(ep * 32 + m) * BS_STRIDE + j] + bias;
                v = fmaxf(v, 0.f);
                s += v;
                ss = fmaf(v, v, ss);
            }
            float mean = s * (1.f / NS);
            float var  = (ss - s * mean) * (1.f / (NS - 1));
            float stdv = sqrtf(fmaxf(var, 0.f));
            int e = eg * 4 + ep;
            g_mu[set][e][1 + f]      = mean;
            g_mu[set][e][TT + 1 + f] = stdv;
            const unsigned base = (unsigned)(set * 256 + e) * (2 * LV_KP);
            unsigned short h0, l0, h1, l1;
            split1(mean, h0, l0);
            split1(stdv, h1, l1);
            zh[base + 1 + f]      = h0;  zl[base + 1 + f]      = l0;
            zh[base + TT + 1 + f] = h1;  zl[base + TT + 1 + f] = l1;
        }
    }
}

// ============================================================
// K2: logvar GEMM on tensor cores, cp.async double-buffered.
// Block 64x64, grid (18,8) = 144 blocks, 256 threads.
// Epilogue: +b_lv, clip, pairwise FEATURES (bf16-split) + H/M partials.
// ============================================================
#define LVB_STRIDE 68
#define LV_BUF 35840

__global__ __launch_bounds__(256, 1)
void k_lvgemm(const float* __restrict__ blv)
{
    extern __shared__ unsigned char smem[];

    const int bn  = blockIdx.x;      // N tile (64 cols)
    const int bm  = blockIdx.y;      // M tile (64 rows)
    const int tid = threadIdx.x;
    const int wid = tid >> 5;
    const int lid = tid & 31;
    const int wm  = wid >> 2;
    const int wn  = wid & 3;
    const int gid = lid >> 2;
    const int tig = lid & 3;

    float acc[2][2][4];
    #pragma unroll
    for (int mt = 0; mt < 2; mt++)
        #pragma unroll
        for (int nt = 0; nt < 2; nt++)
            #pragma unroll
            for (int r = 0; r < 4; r++) acc[mt][nt][r] = 0.f;

    auto stage = [&](int c, int buf) {
        unsigned* Aw0 = (unsigned*)(smem + buf * LV_BUF);
        unsigned* Aw1 = (unsigned*)(smem + buf * LV_BUF + 9216);
        unsigned* Bw0 = (unsigned*)(smem + buf * LV_BUF + 18432);
        unsigned* Bw1 = (unsigned*)(smem + buf * LV_BUF + 27136);
        #pragma unroll
        for (int i = 0; i < 2; i++) {
            int u = tid + i * 256;
            int row = u >> 3, kp = (u & 7) * 4;
            unsigned srci = (unsigned)(bm * 64 + row) * LV_KP + c * 32 + kp;
            cp16(s2u(&Aw0[row * AS_STRIDE + kp]), &g_zhi[srci]);
            cp16(s2u(&Aw1[row * AS_STRIDE + kp]), &g_zlo[srci]);
        }
        #pragma unroll
        for (int i = 0; i < 2; i++) {
            int u = tid + i * 256;
            int k2 = u >> 4, nl = (u & 15) * 4;
            unsigned srci = (unsigned)(c * 32 + k2) * LV_NPAD + bn * 64 + nl;
            cp16(s2u(&Bw0[k2 * LVB_STRIDE + nl]), &g_wlvh[srci]);
            cp16(s2u(&Bw1[k2 * LVB_STRIDE + nl]), &g_wlvl[srci]);
        }
        asm volatile("cp.async.commit_group;\n" ::: "memory");
    };

    stage(0, 0);

    for (int chunk = 0; chunk < 17; chunk++) {
        if (chunk < 16) {
            stage(chunk + 1, (chunk + 1) & 1);
            asm volatile("cp.async.wait_group 1;\n" ::: "memory");
        } else {
            asm volatile("cp.async.wait_group 0;\n" ::: "memory");
        }
        __syncthreads();

        const int buf = chunk & 1;
        unsigned* Aw0 = (unsigned*)(smem + buf * LV_BUF);
        unsigned* Aw1 = (unsigned*)(smem + buf * LV_BUF + 9216);
        unsigned* Bw0 = (unsigned*)(smem + buf * LV_BUF + 18432);
        unsigned* Bw1 = (unsigned*)(smem + buf * LV_BUF + 27136);

        #pragma unroll
        for (int ks = 0; ks < 4; ks++) {
            const int cw = ks * 8 + tig;
            unsigned b[2][2][2];
            #pragma unroll
            for (int nt = 0; nt < 2; nt++) {
                int n = wn * 16 + nt * 8 + gid;
                b[nt][0][0] = Bw0[cw * LVB_STRIDE + n];
                b[nt][0][1] = Bw0[(cw + 4) * LVB_STRIDE + n];
                b[nt][1][0] = Bw1[cw * LVB_STRIDE + n];
                b[nt][1][1] = Bw1[(cw + 4) * LVB_STRIDE + n];
            }
            #pragma unroll
            for (int mt = 0; mt < 2; mt++) {
                unsigned a[2][4];
                int r0 = wm * 32 + mt * 16 + gid;
                a[0][0] = Aw0[r0 * AS_STRIDE + cw];
                a[0][1] = Aw0[(r0 + 8) * AS_STRIDE + cw];
                a[0][2] = Aw0[r0 * AS_STRIDE + cw + 4];
                a[0][3] = Aw0[(r0 + 8) * AS_STRIDE + cw + 4];
                a[1][0] = Aw1[r0 * AS_STRIDE + cw];
                a[1][1] = Aw1[(r0 + 8) * AS_STRIDE + cw];
                a[1][2] = Aw1[r0 * AS_STRIDE + cw + 4];
                a[1][3] = Aw1[(r0 + 8) * AS_STRIDE + cw + 4];
                #pragma unroll
                for (int nt = 0; nt < 2; nt++) {
                    mma16816(acc[mt][nt], a[0], b[nt][0]);
                    mma16816(acc[mt][nt], a[0], b[nt][1]);
                    mma16816(acc[mt][nt], a[1], b[nt][0]);
                }
            }
        }
        __syncthreads();
    }

    float* Cs = (float*)smem;                  // [64][68]
    float* hq = (float*)(smem + 17408);        // [64][2]
    float* mq = (float*)(smem + 17920);        // [64][2]
    #pragma unroll
    for (int mt = 0; mt < 2; mt++) {
        int r0 = wm * 32 + mt * 16 + gid;
        #pragma unroll
        for (int nt = 0; nt < 2; nt++) {
            int c = wn * 16 + nt * 8 + tig * 2;
            *(float2*)&Cs[r0 * LVB_STRIDE + c]       = make_float2(acc[mt][nt][0], acc[mt][nt][1]);
            *(float2*)&Cs[(r0 + 8) * LVB_STRIDE + c] = make_float2(acc[mt][nt][2], acc[mt][nt][3]);
        }
    }
    __syncthreads();

    {
        const int j    = tid & 63;          // column within tile
        const int rg   = tid >> 6;          // 0..3 : 16-row group
        const int w2   = (tid >> 5) & 1;
        const int lane = tid & 31;
        const int n = bn * 64 + j;
        const bool valid = (n < T);
        const float bias = valid ? blv[n] : 0.f;
        const int set_blk = (bm >= 4);      // whole block is one set
        const int ebase = (bm & 3) * 64;

        #pragma unroll
        for (int rr = 0; rr < 16; rr++) {
            int r = rg * 16 + rr;
            float lv = fminf(fmaxf(Cs[r * LVB_STRIDE + j] + bias, -9.f), -2.f);
            float h = valid ? lv : 0.f;
            float mm = 0.f;
            if (valid) {
                int e = ebase + r;
                float m   = g_mu[set_blk][e][n];
                float elv = expf(lv);
                float eml = expf(-lv);
                mm = m * m * eml;
                // pairwise features, bf16-split, packed 2 per word
                float f0, f1, f2, f3;
                if (set_blk == 0) {
                    f0 = elv + m * m;  f1 = eml;         f2 = m * eml;    f3 = m;
                } else {
                    f0 = eml;          f1 = elv + m * m; f2 = -2.f * m;   f3 = -2.f * m * eml;
                }
                unsigned short h0, l0, h1, l1, h2, l2, h3, l3;
                split1(f0, h0, l0);
                split1(f1, h1, l1);
                split1(f2, h2, l2);
                split1(f3, h3, l3);
                unsigned whi0 = (unsigned)h0 | ((unsigned)h1 << 16);
                unsigned wlo0 = (unsigned)l0 | ((unsigned)l1 << 16);
                unsigned whi1 = (unsigned)h2 | ((unsigned)h3 << 16);
                unsigned wlo1 = (unsigned)l2 | ((unsigned)l3 << 16);
                unsigned widx = (unsigned)e * PK_STRIDE + 2 * n;
                if (set_blk == 0) {
                    *(uint2*)&g_pAhi[widx] = make_uint2(whi0, whi1);
                    *(uint2*)&g_pAlo[widx] = make_uint2(wlo0, wlo1);
                } else {
                    *(uint2*)&g_pBhi[widx] = make_uint2(whi0, whi1);
                    *(uint2*)&g_pBlo[widx] = make_uint2(wlo0, wlo1);
                }
            }
            #pragma unroll
            for (int off = 16; off > 0; off >>= 1) {
                h  += __shfl_down_sync(0xffffffffu, h,  off);
                mm += __shfl_down_sync(0xffffffffu, mm, off);
            }
            if (lane == 0) { hq[r * 2 + w2] = h; mq[r * 2 + w2] = mm; }
        }
    }
    __syncthreads();
    if (tid < 64) {
        g_Hpart[bn][bm * 64 + tid] = hq[tid * 2] + hq[tid * 2 + 1];
        g_Mpart[bn][bm * 64 + tid] = mq[tid * 2] + mq[tid * 2 + 1];
    }
}

// ============================================================
// K3: pairwise GEMM on tensor cores: spart[z][i][j] = sum_k A[i,k]*B[j,k]
// over chunks {z, z+8, ...} < 65.  Block 64x64, grid (4,4,8), 256 threads.
// Both A and B stored row-major (k contiguous) — B fragment reads transposed.
// ============================================================
#define PG_BUF 36864

__global__ __launch_bounds__(256, 1)
void k_pgemm()
{
    extern __shared__ unsigned char smem[];
    const int j0  = blockIdx.x * 64;
    const int i0  = blockIdx.y * 64;
    const int bz  = blockIdx.z;
    const int tid = threadIdx.x;
    const int wid = tid >> 5;
    const int lid = tid & 31;
    const int wm  = wid >> 2;        // 0..1 : 32-row warp tile
    const int wn  = wid & 3;         // 0..3 : 16-col warp tile
    const int gid = lid >> 2;
    const int tig = lid & 3;

    float acc[2][2][4];
    #pragma unroll
    for (int mt = 0; mt < 2; mt++)
        #pragma unroll
        for (int nt = 0; nt < 2; nt++)
            #pragma unroll
            for (int r = 0; r < 4; r++) acc[mt][nt][r] = 0.f;

    auto stage = [&](int c, int buf) {
        unsigned* Ah = (unsigned*)(smem + buf * PG_BUF);
        unsigned* Al = (unsigned*)(smem + buf * PG_BUF + 9216);
        unsigned* Bh = (unsigned*)(smem + buf * PG_BUF + 18432);
        unsigned* Bl = (unsigned*)(smem + buf * PG_BUF + 27648);
        #pragma unroll
        for (int i = 0; i < 2; i++) {
            int u = tid + i * 256;
            int row = u >> 3, kp = (u & 7) * 4;
            unsigned sa = (unsigned)(i0 + row) * PK_STRIDE + c * 32 + kp;
            unsigned sb = (unsigned)(j0 + row) * PK_STRIDE + c * 32 + kp;
            cp16(s2u(&Ah[row * AS_STRIDE + kp]), &g_pAhi[sa]);
            cp16(s2u(&Al[row * AS_STRIDE + kp]), &g_pAlo[sa]);
            cp16(s2u(&Bh[row * AS_STRIDE + kp]), &g_pBhi[sb]);
            cp16(s2u(&Bl[row * AS_STRIDE + kp]), &g_pBlo[sb]);
        }
        asm volatile("cp.async.commit_group;\n" ::: "memory");
    };

    stage(bz, 0);

    int buf = 0;
    for (int c = bz; c < PK_CHUNKS; c += 8, buf ^= 1) {
        int nc = c + 8;
        if (nc < PK_CHUNKS) {
            stage(nc, buf ^ 1);
            asm volatile("cp.async.wait_group 1;\n" ::: "memory");
        } else {
            asm volatile("cp.async.wait_group 0;\n" ::: "memory");
        }
        __syncthreads();

        unsigned* Ah = (unsigned*)(smem + buf * PG_BUF);
        unsigned* Al = (unsigned*)(smem + buf * PG_BUF + 9216);
        unsigned* Bh = (unsigned*)(smem + buf * PG_BUF + 18432);
        unsigned* Bl = (unsigned*)(smem + buf * PG_BUF + 27648);

        #pragma unroll
        for (int ks = 0; ks < 4; ks++) {
            const int cw = ks * 8 + tig;
            unsigned b[2][2][2];
            #pragma unroll
            for (int nt = 0; nt < 2; nt++) {
                int n = wn * 16 + nt * 8 + gid;
                b[nt][0][0] = Bh[n * AS_STRIDE + cw];
                b[nt][0][1] = Bh[n * AS_STRIDE + cw + 4];
                b[nt][1][0] = Bl[n * AS_STRIDE + cw];
                b[nt][1][1] = Bl[n * AS_STRIDE + cw + 4];
            }
            #pragma unroll
            for (int mt = 0; mt < 2; mt++) {
                unsigned a[2][4];
                int r0 = wm * 32 + mt * 16 + gid;
                a[0][0] = Ah[r0 * AS_STRIDE + cw];
                a[0][1] = Ah[(r0 + 8) * AS_STRIDE + cw];
                a[0][2] = Ah[r0 * AS_STRIDE + cw + 4];
                a[0][3] = Ah[(r0 + 8) * AS_STRIDE + cw + 4];
                a[1][0] = Al[r0 * AS_STRIDE + cw];
                a[1][1] = Al[(r0 + 8) * AS_STRIDE + cw];
                a[1][2] = Al[r0 * AS_STRIDE + cw + 4];
                a[1][3] = Al[(r0 + 8) * AS_STRIDE + cw + 4];
                #pragma unroll
                for (int nt = 0; nt < 2; nt++) {
                    mma16816(acc[mt][nt], a[0], b[nt][0]);
                    mma16816(acc[mt][nt], a[0], b[nt][1]);
                    mma16816(acc[mt][nt], a[1], b[nt][0]);
                }
            }
        }
        __syncthreads();
    }

    #pragma unroll
    for (int mt = 0; mt < 2; mt++) {
        int r0 = i0 + wm * 32 + mt * 16 + gid;
        #pragma unroll
        for (int nt = 0; nt < 2; nt++) {
            int c = j0 + wn * 16 + nt * 8 + tig * 2;
            *(float2*)&g_spart[bz][r0][c]     = make_float2(acc[mt][nt][0], acc[mt][nt][1]);
            *(float2*)&g_spart[bz][r0 + 8][c] = make_float2(acc[mt][nt][2], acc[mt][nt][3]);
        }
    }
}

// ============================================================
// K4: assemble score + log_softmax + classes tail.
// score = 0.5*(pairsum + M0[i] + M1[j]) - T + H0[i] + H1[j]
// ============================================================
__global__ void k_softmax(float* __restrict__ out, int out_size)
{
    const int i = blockIdx.x;
    const int j = threadIdx.x;
    __shared__ float red[256];

    float s = 0.f;
    #pragma unroll
    for (int z = 0; z < 8; z++) s += g_spart[z][i][j];

    float H0 = 0.5f * (float)T * LOG_2PIE;
    float H1 = H0;
    float M0 = 0.f, M1 = 0.f;
    #pragma unroll
    for (int b = 0; b < 18; b++) {
        H0 += g_Hpart[b][i];
        H1 += g_Hpart[b][NEP + j];
        M0 += g_Mpart[b][i];
        M1 += g_Mpart[b][NEP + j];
    }
    float score = 0.5f * (s + M0 + M1) - (float)T + H0 + H1;
    float v = -score;

    red[j] = v;
    __syncthreads();
    for (int st = 128; st > 0; st >>= 1) {
        if (j < st) red[j] = fmaxf(red[j], red[j + st]);
        __syncthreads();
    }
    float mx = red[0];
    __syncthreads();
    float ex = expf(v - mx);
    red[j] = ex;
    __syncthreads();
    for (int st = 128; st > 0; st >>= 1) {
        if (j < st) red[j] += red[j + st];
        __syncthreads();
    }
    float lse = mx + logf(red[0]);
    out[(size_t)i * NEP + j] = v - lse;

    if (j == 0 && NEP * NEP + i < out_size)
        out[NEP * NEP + i] = (float)i;
}

// ============================================================
extern "C" void kernel_launch(void* const* d_in, const int* in_sizes, int n_in,
                              void* d_out, int out_size)
{
    const float* train_inputs  = (const float*)d_in[0];
    const float* train_targets = (const float*)d_in[1];
    const float* test_inputs   = (const float*)d_in[2];
    const float* test_targets  = (const float*)d_in[3];
    const float* W_fe          = (const float*)d_in[4];
    const float* b_fe          = (const float*)d_in[5];
    const float* W_lv          = (const float*)d_in[6];
    const float* b_lv          = (const float*)d_in[7];
    float* out = (float*)d_out;

    const int smem_fgemm = 2 * FG_BUF;           // 141312
    const int smem_lv    = 2 * LV_BUF;           // 71680
    const int smem_pg    = 2 * PG_BUF;           // 73728
    cudaFuncSetAttribute(k_fgemm,  cudaFuncAttributeMaxDynamicSharedMemorySize, smem_fgemm);
    cudaFuncSetAttribute(k_lvgemm, cudaFuncAttributeMaxDynamicSharedMemorySize, smem_lv);
    cudaFuncSetAttribute(k_pgemm,  cudaFuncAttributeMaxDynamicSharedMemorySize, smem_pg);

    k_prep<<<19408, 256>>>(train_inputs, test_inputs, W_fe, W_lv,
                           train_targets, test_targets);
    k_fgemm<<<dim3(4, 64, 2), 256, smem_fgemm>>>(b_fe);
    k_lvgemm<<<dim3(18, 8), 256, smem_lv>>>(b_lv);
    k_pgemm<<<dim3(4, 4, 8), 256, smem_pg>>>();
    k_softmax<<<NEP, 256>>>(out, out_size);
}